// round 2
// baseline (speedup 1.0000x reference)
#include <cuda_runtime.h>

#define Bq 2
#define Sq 2048
#define Dm 1024
#define Hh 16
#define DKq 64
#define NROWS (Bq*Sq)      // 4096
#define BH (Bq*Hh)         // 32

// -------- device scratch (allocation-free rule: use __device__ globals) -----
__device__ float g_q[BH * Sq * DKq];    // [B,H,S,DK]
__device__ float g_k[BH * Sq * DKq];
__device__ float g_v[BH * Sq * DKq];
__device__ float g_ctx[NROWS * Dm];     // [B,S,D]

// ---------------------------------------------------------------------------
// GEMM (NT): C[M,N] = A[M,K] @ W[N,K]^T + bias[N]
// 128x128 tile, TK=16, 256 threads, 8x8 microtile.
// split==1: store C with head-split layout [B,H,S,DK] (for Q/K/V)
// ---------------------------------------------------------------------------
__global__ __launch_bounds__(256) void gemm_nt(
    const float* __restrict__ A, const float* __restrict__ W,
    const float* __restrict__ bias, float* __restrict__ C,
    int M, int N, int K, int split)
{
    __shared__ float As[16][128];
    __shared__ float Bs[16][128];
    const int t  = threadIdx.x;
    const int m0 = blockIdx.y * 128;
    const int n0 = blockIdx.x * 128;
    const int tx = t & 15;
    const int ty = t >> 4;

    float acc[8][8];
#pragma unroll
    for (int i = 0; i < 8; i++)
#pragma unroll
        for (int j = 0; j < 8; j++) acc[i][j] = 0.f;

    for (int k0 = 0; k0 < K; k0 += 16) {
#pragma unroll
        for (int l = 0; l < 2; l++) {
            int idx = t + l * 256;          // 0..511 float4 slots
            int row = idx >> 2;             // 0..127
            int c4  = (idx & 3) * 4;        // 0,4,8,12
            float4 av = *(const float4*)(A + (size_t)(m0 + row) * K + k0 + c4);
            As[c4 + 0][row] = av.x; As[c4 + 1][row] = av.y;
            As[c4 + 2][row] = av.z; As[c4 + 3][row] = av.w;
            float4 wv = *(const float4*)(W + (size_t)(n0 + row) * K + k0 + c4);
            Bs[c4 + 0][row] = wv.x; Bs[c4 + 1][row] = wv.y;
            Bs[c4 + 2][row] = wv.z; Bs[c4 + 3][row] = wv.w;
        }
        __syncthreads();
#pragma unroll
        for (int kk = 0; kk < 16; kk++) {
            float a[8], b[8];
            *(float4*)&a[0] = *(const float4*)&As[kk][ty * 8];
            *(float4*)&a[4] = *(const float4*)&As[kk][ty * 8 + 4];
            *(float4*)&b[0] = *(const float4*)&Bs[kk][tx * 8];
            *(float4*)&b[4] = *(const float4*)&Bs[kk][tx * 8 + 4];
#pragma unroll
            for (int i = 0; i < 8; i++)
#pragma unroll
                for (int j = 0; j < 8; j++)
                    acc[i][j] = fmaf(a[i], b[j], acc[i][j]);
        }
        __syncthreads();
    }

#pragma unroll
    for (int i = 0; i < 8; i++) {
        int m = m0 + ty * 8 + i;
#pragma unroll
        for (int j = 0; j < 8; j++) {
            int n = n0 + tx * 8 + j;
            float val = acc[i][j] + bias[n];
            if (!split) {
                C[(size_t)m * N + n] = val;
            } else {
                int b = m / Sq, s = m % Sq;
                int h = n / DKq, dk = n % DKq;
                C[(((size_t)(b * Hh + h)) * Sq + s) * DKq + dk] = val;
            }
        }
    }
}

// ---------------------------------------------------------------------------
// scores: P[bh, q, k] = scale * dot(Q[bh,q,:], K[bh,k,:])  -> attn buffer
// 64x64 output tile per block, full DK=64 in smem.
// ---------------------------------------------------------------------------
__global__ __launch_bounds__(256) void scores_kernel(float* __restrict__ attn)
{
    __shared__ float Qs[64][65];
    __shared__ float Ks[64][65];
    const int bh = blockIdx.z;
    const int q0 = blockIdx.y * 64;
    const int k0 = blockIdx.x * 64;
    const float* Q  = g_q + (size_t)bh * Sq * DKq;
    const float* Kp = g_k + (size_t)bh * Sq * DKq;
    const int t = threadIdx.x;

#pragma unroll
    for (int l = 0; l < 4; l++) {
        int idx = t + l * 256;              // 0..1023 float4 slots
        int row = idx >> 4;                 // 0..63
        int c4  = (idx & 15) * 4;           // 0..60
        float4 qv = *(const float4*)(Q + (size_t)(q0 + row) * DKq + c4);
        Qs[row][c4 + 0] = qv.x; Qs[row][c4 + 1] = qv.y;
        Qs[row][c4 + 2] = qv.z; Qs[row][c4 + 3] = qv.w;
        float4 kv = *(const float4*)(Kp + (size_t)(k0 + row) * DKq + c4);
        Ks[row][c4 + 0] = kv.x; Ks[row][c4 + 1] = kv.y;
        Ks[row][c4 + 2] = kv.z; Ks[row][c4 + 3] = kv.w;
    }
    __syncthreads();

    const int tx = t & 15, ty = t >> 4;
    float acc[4][4];
#pragma unroll
    for (int i = 0; i < 4; i++)
#pragma unroll
        for (int j = 0; j < 4; j++) acc[i][j] = 0.f;

#pragma unroll 8
    for (int kk = 0; kk < 64; kk++) {
        float a[4], b[4];
#pragma unroll
        for (int i = 0; i < 4; i++) a[i] = Qs[ty * 4 + i][kk];
#pragma unroll
        for (int j = 0; j < 4; j++) b[j] = Ks[tx * 4 + j][kk];
#pragma unroll
        for (int i = 0; i < 4; i++)
#pragma unroll
            for (int j = 0; j < 4; j++)
                acc[i][j] = fmaf(a[i], b[j], acc[i][j]);
    }

    const float scale = 0.125f;  // 1/sqrt(64)
    float* P = attn + (size_t)bh * Sq * Sq;
#pragma unroll
    for (int i = 0; i < 4; i++) {
        float4 o = make_float4(acc[i][0] * scale, acc[i][1] * scale,
                               acc[i][2] * scale, acc[i][3] * scale);
        *(float4*)(P + (size_t)(q0 + ty * 4 + i) * Sq + k0 + tx * 4) = o;
    }
}

// ---------------------------------------------------------------------------
// softmax over last dim (row length S=2048), one block (256 thr) per row.
// ---------------------------------------------------------------------------
__global__ __launch_bounds__(256) void softmax_kernel(float* __restrict__ attn)
{
    const size_t row = blockIdx.x;
    float* P = attn + row * Sq;
    const int t = threadIdx.x;
    __shared__ float red[256];

    float4 v0 = ((const float4*)P)[t];
    float4 v1 = ((const float4*)P)[t + 256];

    float m = fmaxf(fmaxf(fmaxf(v0.x, v0.y), fmaxf(v0.z, v0.w)),
                    fmaxf(fmaxf(v1.x, v1.y), fmaxf(v1.z, v1.w)));
    red[t] = m;
    __syncthreads();
#pragma unroll
    for (int s = 128; s > 0; s >>= 1) {
        if (t < s) red[t] = fmaxf(red[t], red[t + s]);
        __syncthreads();
    }
    const float mx = red[0];
    __syncthreads();

    v0.x = __expf(v0.x - mx); v0.y = __expf(v0.y - mx);
    v0.z = __expf(v0.z - mx); v0.w = __expf(v0.w - mx);
    v1.x = __expf(v1.x - mx); v1.y = __expf(v1.y - mx);
    v1.z = __expf(v1.z - mx); v1.w = __expf(v1.w - mx);

    float s8 = (v0.x + v0.y + v0.z + v0.w) + (v1.x + v1.y + v1.z + v1.w);
    red[t] = s8;
    __syncthreads();
#pragma unroll
    for (int s = 128; s > 0; s >>= 1) {
        if (t < s) red[t] += red[t + s];
        __syncthreads();
    }
    const float inv = 1.0f / red[0];

    v0.x *= inv; v0.y *= inv; v0.z *= inv; v0.w *= inv;
    v1.x *= inv; v1.y *= inv; v1.z *= inv; v1.w *= inv;
    ((float4*)P)[t] = v0;
    ((float4*)P)[t + 256] = v1;
}

// ---------------------------------------------------------------------------
// av: ctx[b, q, h*64+d] = sum_k P[bh,q,k] * V[bh,k,d]
// Block: 128 q-rows x 64 (all DK), k-tile 32.
// ---------------------------------------------------------------------------
__global__ __launch_bounds__(256) void av_kernel(const float* __restrict__ attn)
{
    __shared__ float Ps[128][33];
    __shared__ float Vs[32][64];
    const int bh = blockIdx.y;
    const int q0 = blockIdx.x * 128;
    const float* P = attn + (size_t)bh * Sq * Sq;
    const float* V = g_v + (size_t)bh * Sq * DKq;
    const int b = bh / Hh, h = bh % Hh;
    const int t = threadIdx.x;
    const int tx = t & 15, ty = t >> 4;

    float acc[8][4];
#pragma unroll
    for (int i = 0; i < 8; i++)
#pragma unroll
        for (int j = 0; j < 4; j++) acc[i][j] = 0.f;

    for (int k0 = 0; k0 < Sq; k0 += 32) {
#pragma unroll
        for (int l = 0; l < 4; l++) {
            int idx = t + l * 256;          // 0..1023 float4 slots
            int row = idx >> 3;             // 0..127
            int c4  = (idx & 7) * 4;        // 0..28
            float4 pv = *(const float4*)(P + (size_t)(q0 + row) * Sq + k0 + c4);
            Ps[row][c4 + 0] = pv.x; Ps[row][c4 + 1] = pv.y;
            Ps[row][c4 + 2] = pv.z; Ps[row][c4 + 3] = pv.w;
        }
#pragma unroll
        for (int l = 0; l < 2; l++) {
            int idx = t + l * 256;          // 0..511 float4 slots
            int row = idx >> 4;             // 0..31
            int c4  = (idx & 15) * 4;       // 0..60
            *(float4*)&Vs[row][c4] = *(const float4*)(V + (size_t)(k0 + row) * DKq + c4);
        }
        __syncthreads();
#pragma unroll 8
        for (int kk = 0; kk < 32; kk++) {
            float pr[8], vr[4];
#pragma unroll
            for (int i = 0; i < 8; i++) pr[i] = Ps[ty * 8 + i][kk];
            *(float4*)vr = *(const float4*)&Vs[kk][tx * 4];
#pragma unroll
            for (int i = 0; i < 8; i++)
#pragma unroll
                for (int j = 0; j < 4; j++)
                    acc[i][j] = fmaf(pr[i], vr[j], acc[i][j]);
        }
        __syncthreads();
    }

#pragma unroll
    for (int i = 0; i < 8; i++) {
        int qrow = q0 + ty * 8 + i;
        float4 o = make_float4(acc[i][0], acc[i][1], acc[i][2], acc[i][3]);
        *(float4*)&g_ctx[((size_t)(b * Sq + qrow)) * Dm + h * DKq + tx * 4] = o;
    }
}

// ---------------------------------------------------------------------------
extern "C" void kernel_launch(void* const* d_in, const int* in_sizes, int n_in,
                              void* d_out, int out_size)
{
    const float* x  = (const float*)d_in[0];
    const float* Wq = (const float*)d_in[1];
    const float* bq = (const float*)d_in[2];
    const float* Wk = (const float*)d_in[3];
    const float* bk = (const float*)d_in[4];
    const float* Wv = (const float*)d_in[5];
    const float* bv = (const float*)d_in[6];
    const float* Wo = (const float*)d_in[7];
    const float* bo = (const float*)d_in[8];

    float* out  = (float*)d_out;
    float* attn = out + (size_t)NROWS * Dm;   // outputs concatenated: out, attn

    float *q, *k, *v, *ctx;
    cudaGetSymbolAddress((void**)&q,   g_q);
    cudaGetSymbolAddress((void**)&k,   g_k);
    cudaGetSymbolAddress((void**)&v,   g_v);
    cudaGetSymbolAddress((void**)&ctx, g_ctx);

    dim3 gProj(Dm / 128, NROWS / 128);   // (8, 32)
    gemm_nt<<<gProj, 256>>>(x, Wq, bq, q, NROWS, Dm, Dm, 1);
    gemm_nt<<<gProj, 256>>>(x, Wk, bk, k, NROWS, Dm, Dm, 1);
    gemm_nt<<<gProj, 256>>>(x, Wv, bv, v, NROWS, Dm, Dm, 1);

    dim3 gScores(Sq / 64, Sq / 64, BH);  // (32, 32, 32)
    scores_kernel<<<gScores, 256>>>(attn);

    softmax_kernel<<<BH * Sq, 256>>>(attn);

    dim3 gAV(Sq / 128, BH);              // (16, 32)
    av_kernel<<<gAV, 256>>>(attn);

    gemm_nt<<<gProj, 256>>>(ctx, Wo, bo, out, NROWS, Dm, Dm, 0);
}

// round 3
// speedup vs baseline: 2.2137x; 2.2137x over previous
#include <cuda_runtime.h>
#include <cuda_bf16.h>

#define Bq 2
#define Sq 2048
#define Dm 1024
#define Hh 16
#define DKq 64
#define NROWS (Bq*Sq)      // 4096
#define BH (Bq*Hh)         // 32

typedef __nv_bfloat16 bf16;
typedef __nv_bfloat162 bf162;

// -------- device scratch (allocation-free rule: __device__ globals) ---------
__device__ bf16 g_xh[NROWS*Dm], g_xl[NROWS*Dm];
__device__ bf16 g_wh[4*Dm*Dm],  g_wl[4*Dm*Dm];
__device__ bf16 g_qh[BH*Sq*DKq], g_ql[BH*Sq*DKq];
__device__ bf16 g_kh[BH*Sq*DKq], g_kl[BH*Sq*DKq];
__device__ bf16 g_vh[BH*Sq*DKq], g_vl[BH*Sq*DKq];
__device__ bf16 g_ph[(size_t)BH*Sq*Sq], g_pl[(size_t)BH*Sq*Sq];
__device__ bf16 g_ch[NROWS*Dm], g_cl[NROWS*Dm];

// ------------------------------- PTX helpers --------------------------------
#define LDSM4(r0,r1,r2,r3,addr) \
    asm volatile("ldmatrix.sync.aligned.m8n8.x4.shared.b16 {%0,%1,%2,%3},[%4];" \
                 : "=r"(r0),"=r"(r1),"=r"(r2),"=r"(r3) : "r"(addr))
#define LDSM4T(r0,r1,r2,r3,addr) \
    asm volatile("ldmatrix.sync.aligned.m8n8.x4.trans.shared.b16 {%0,%1,%2,%3},[%4];" \
                 : "=r"(r0),"=r"(r1),"=r"(r2),"=r"(r3) : "r"(addr))
#define MMA16816(ac,a,b) \
    asm volatile("mma.sync.aligned.m16n8k16.row.col.f32.bf16.bf16.f32 " \
                 "{%0,%1,%2,%3},{%4,%5,%6,%7},{%8,%9},{%0,%1,%2,%3};" \
                 : "+f"((ac)[0]),"+f"((ac)[1]),"+f"((ac)[2]),"+f"((ac)[3]) \
                 : "r"((a)[0]),"r"((a)[1]),"r"((a)[2]),"r"((a)[3]), \
                   "r"((b)[0]),"r"((b)[1]))
#define CPASYNC16(dst,src) \
    asm volatile("cp.async.cg.shared.global [%0],[%1],16;" \
                 :: "r"(dst), "l"(__cvta_generic_to_global((const void*)(src))))
#define CPCOMMIT asm volatile("cp.async.commit_group;")
#define CPWAIT0  asm volatile("cp.async.wait_group 0;")

__device__ __forceinline__ unsigned smaddr(const void* p) {
    return (unsigned)__cvta_generic_to_shared(p);
}

__device__ __forceinline__ void split2(float x, float y, bf16* hp, bf16* lp) {
    bf16 hx = __float2bfloat16(x), hy = __float2bfloat16(y);
    float lx = x - __bfloat162float(hx), ly = y - __bfloat162float(hy);
    *(bf162*)hp = __halves2bfloat162(hx, hy);
    *(bf162*)lp = __halves2bfloat162(__float2bfloat16(lx), __float2bfloat16(ly));
}

// ------------------------------- split kernel -------------------------------
__global__ __launch_bounds__(256) void split_kernel(
    const float* __restrict__ src, bf16* __restrict__ hi, bf16* __restrict__ lo, int n4)
{
    int i = blockIdx.x * blockDim.x + threadIdx.x;
    if (i >= n4) return;
    float4 v = ((const float4*)src)[i];
    split2(v.x, v.y, hi + (size_t)i*4,     lo + (size_t)i*4);
    split2(v.z, v.w, hi + (size_t)i*4 + 2, lo + (size_t)i*4 + 2);
}

// ---------------------------------------------------------------------------
// Generic NT GEMM on hi/lo bf16 pairs: C = scale*(A @ W^T) (+bias)
// Block 128x128, ktile 32, 8 warps (2m x 4n), warp tile 64x32, double-buffered
// cp.async. mode 0: write hi/lo bf16 with head-split layout [B,H,S,DK].
// mode 1: write fp32 rows (ldc), per-z offset strideC.
// ---------------------------------------------------------------------------
#define NT_STAGE_H 20480   // halves per stage: 4 matrices * 128*40

__device__ __forceinline__ void nt_load(
    unsigned sb,
    const bf16* __restrict__ Ah, const bf16* __restrict__ Al,
    const bf16* __restrict__ Wh, const bf16* __restrict__ Wl,
    int lda, int ldw, int m0, int n0, int kt, int t)
{
#pragma unroll
    for (int j = 0; j < 2; j++) {
        int idx = t + j*256;
        int row = idx >> 2;
        int q   = (idx & 3) * 8;
        unsigned so = (unsigned)(row*40 + q) * 2;
        CPASYNC16(sb + so,               Ah + (size_t)(m0+row)*lda + kt + q);
        CPASYNC16(sb + 5120*2  + so,     Al + (size_t)(m0+row)*lda + kt + q);
        CPASYNC16(sb + 10240*2 + so,     Wh + (size_t)(n0+row)*ldw + kt + q);
        CPASYNC16(sb + 15360*2 + so,     Wl + (size_t)(n0+row)*ldw + kt + q);
    }
}

__global__ __launch_bounds__(256) void gemm_bf16x2_nt(
    const bf16* __restrict__ Ah, const bf16* __restrict__ Al, int lda, long long strideA,
    const bf16* __restrict__ Wh, const bf16* __restrict__ Wl, int ldw, long long strideW,
    const float* __restrict__ bias,
    float* __restrict__ outF, long long strideC, int ldc,
    bf16* __restrict__ outHi, bf16* __restrict__ outLo,
    int K, float scale, int mode)
{
    extern __shared__ bf16 sm[];
    const int t    = threadIdx.x;
    const int lane = t & 31;
    const int wid  = t >> 5;
    const int warp_m = wid >> 2;    // 0..1  (x64)
    const int warp_n = wid & 3;     // 0..3  (x32)
    const int m0 = blockIdx.y * 128;
    const int n0 = blockIdx.x * 128;
    const int z  = blockIdx.z;

    Ah += (size_t)z * strideA;  Al += (size_t)z * strideA;
    Wh += (size_t)z * strideW;  Wl += (size_t)z * strideW;

    float acc[4][4][4];
#pragma unroll
    for (int i = 0; i < 4; i++)
#pragma unroll
        for (int j = 0; j < 4; j++)
#pragma unroll
            for (int r = 0; r < 4; r++) acc[i][j][r] = 0.f;

    const unsigned s0 = smaddr(sm);
    const int nk = K / 32;

    nt_load(s0, Ah, Al, Wh, Wl, lda, ldw, m0, n0, 0, t);
    CPCOMMIT;

    for (int i = 0; i < nk; i++) {
        CPWAIT0;
        __syncthreads();
        if (i + 1 < nk) {
            nt_load(s0 + ((i+1)&1)*NT_STAGE_H*2, Ah, Al, Wh, Wl, lda, ldw,
                    m0, n0, (i+1)*32, t);
            CPCOMMIT;
        }
        unsigned sb = s0 + (i&1)*NT_STAGE_H*2;

#pragma unroll
        for (int k16 = 0; k16 < 32; k16 += 16) {
            unsigned ah[4][4], al[4][4], bh[4][2], bl[4][2];
            int arow = warp_m*64 + (lane & 15);
            int acol = k16 + ((lane >> 4) << 3);
#pragma unroll
            for (int mt = 0; mt < 4; mt++) {
                unsigned ad = sb + (unsigned)((arow + mt*16)*40 + acol)*2;
                LDSM4(ah[mt][0], ah[mt][1], ah[mt][2], ah[mt][3], ad);
                LDSM4(al[mt][0], al[mt][1], al[mt][2], al[mt][3], ad + 5120*2);
            }
            int brow = warp_n*32 + ((lane >> 4) << 3) + (lane & 7);
            int bcol = k16 + (((lane >> 3) & 1) << 3);
#pragma unroll
            for (int pr = 0; pr < 2; pr++) {
                unsigned bd = sb + 10240*2 + (unsigned)((brow + pr*16)*40 + bcol)*2;
                unsigned r0, r1, r2, r3;
                LDSM4(r0, r1, r2, r3, bd);
                bh[pr*2][0] = r0; bh[pr*2][1] = r1;
                bh[pr*2+1][0] = r2; bh[pr*2+1][1] = r3;
                LDSM4(r0, r1, r2, r3, bd + 5120*2);
                bl[pr*2][0] = r0; bl[pr*2][1] = r1;
                bl[pr*2+1][0] = r2; bl[pr*2+1][1] = r3;
            }
#pragma unroll
            for (int mt = 0; mt < 4; mt++)
#pragma unroll
                for (int nt = 0; nt < 4; nt++) {
                    MMA16816(acc[mt][nt], ah[mt], bh[nt]);
                    MMA16816(acc[mt][nt], ah[mt], bl[nt]);
                    MMA16816(acc[mt][nt], al[mt], bh[nt]);
                }
        }
    }

    // ----------------------------- epilogue --------------------------------
#pragma unroll
    for (int mt = 0; mt < 4; mt++)
#pragma unroll
        for (int nt = 0; nt < 4; nt++) {
            int r = m0 + warp_m*64 + mt*16 + (lane >> 2);
            int c = n0 + warp_n*32 + nt*8 + ((lane & 3) << 1);
            float b0v = bias ? bias[c]   : 0.f;
            float b1v = bias ? bias[c+1] : 0.f;
            float v00 = acc[mt][nt][0]*scale + b0v;
            float v01 = acc[mt][nt][1]*scale + b1v;
            float v10 = acc[mt][nt][2]*scale + b0v;
            float v11 = acc[mt][nt][3]*scale + b1v;
            if (mode == 1) {
                float* Cz = outF + (size_t)z * strideC;
                float2 lo2 = make_float2(v00, v01);
                float2 hi2 = make_float2(v10, v11);
                *(float2*)&Cz[(size_t)r*ldc + c]     = lo2;
                *(float2*)&Cz[(size_t)(r+8)*ldc + c] = hi2;
            } else {
                int b = r >> 11, s = r & 2047;
                int h = c >> 6,  dk = c & 63;
                size_t base = (((size_t)(b*Hh + h))*Sq + s)*DKq + dk;
                split2(v00, v01, outHi + base, outLo + base);
                split2(v10, v11, outHi + base + 8*DKq, outLo + base + 8*DKq);
            }
        }
}

// ---------------------------------------------------------------------------
// softmax over last dim (2048) + emit bf16 hi/lo split of P
// ---------------------------------------------------------------------------
__global__ __launch_bounds__(256) void softmax_split(
    float* __restrict__ attn, bf16* __restrict__ ph, bf16* __restrict__ pl)
{
    const size_t row = blockIdx.x;
    float* P = attn + row * Sq;
    const int t = threadIdx.x;
    __shared__ float red[256];

    float4 v0 = ((const float4*)P)[t];
    float4 v1 = ((const float4*)P)[t + 256];

    float m = fmaxf(fmaxf(fmaxf(v0.x, v0.y), fmaxf(v0.z, v0.w)),
                    fmaxf(fmaxf(v1.x, v1.y), fmaxf(v1.z, v1.w)));
    red[t] = m;
    __syncthreads();
#pragma unroll
    for (int s = 128; s > 0; s >>= 1) {
        if (t < s) red[t] = fmaxf(red[t], red[t + s]);
        __syncthreads();
    }
    const float mx = red[0];
    __syncthreads();

    v0.x = __expf(v0.x - mx); v0.y = __expf(v0.y - mx);
    v0.z = __expf(v0.z - mx); v0.w = __expf(v0.w - mx);
    v1.x = __expf(v1.x - mx); v1.y = __expf(v1.y - mx);
    v1.z = __expf(v1.z - mx); v1.w = __expf(v1.w - mx);

    float s8 = (v0.x + v0.y + v0.z + v0.w) + (v1.x + v1.y + v1.z + v1.w);
    red[t] = s8;
    __syncthreads();
#pragma unroll
    for (int s = 128; s > 0; s >>= 1) {
        if (t < s) red[t] += red[t + s];
        __syncthreads();
    }
    const float inv = 1.0f / red[0];

    v0.x *= inv; v0.y *= inv; v0.z *= inv; v0.w *= inv;
    v1.x *= inv; v1.y *= inv; v1.z *= inv; v1.w *= inv;
    ((float4*)P)[t]       = v0;
    ((float4*)P)[t + 256] = v1;

    size_t o0 = row * Sq + t*4;
    size_t o1 = o0 + 1024;
    split2(v0.x, v0.y, ph + o0,     pl + o0);
    split2(v0.z, v0.w, ph + o0 + 2, pl + o0 + 2);
    split2(v1.x, v1.y, ph + o1,     pl + o1);
    split2(v1.z, v1.w, ph + o1 + 2, pl + o1 + 2);
}

// ---------------------------------------------------------------------------
// AV (NN): ctx[b,q,h*64+d] = sum_k P[bh,q,k] * V[bh,k,d]
// Block 128q x 64d, ktile 32, 8 warps (4m x 2n), warp tile 32x32.
// P fragments via ldmatrix, V fragments via ldmatrix.trans.
// ---------------------------------------------------------------------------
#define AV_STAGE_H 14848   // 2*128*40 + 2*32*72 halves

__device__ __forceinline__ void av_load(
    unsigned sb,
    const bf16* __restrict__ Ph, const bf16* __restrict__ Pl,
    const bf16* __restrict__ Vh, const bf16* __restrict__ Vl,
    int q0, int kt, int t)
{
#pragma unroll
    for (int j = 0; j < 2; j++) {
        int idx = t + j*256;
        int row = idx >> 2;
        int q   = (idx & 3) * 8;
        unsigned so = (unsigned)(row*40 + q) * 2;
        CPASYNC16(sb + so,            Ph + (size_t)(q0+row)*Sq + kt + q);
        CPASYNC16(sb + 5120*2 + so,   Pl + (size_t)(q0+row)*Sq + kt + q);
    }
    {
        int row = t >> 3;          // 0..31
        int q   = (t & 7) * 8;     // 0..56
        unsigned so = (unsigned)(row*72 + q) * 2;
        CPASYNC16(sb + 10240*2 + so,          Vh + (size_t)(kt+row)*DKq + q);
        CPASYNC16(sb + (10240+2304)*2 + so,   Vl + (size_t)(kt+row)*DKq + q);
    }
}

__global__ __launch_bounds__(256) void av_bf16x2(
    const bf16* __restrict__ Ph_g, const bf16* __restrict__ Pl_g,
    const bf16* __restrict__ Vh_g, const bf16* __restrict__ Vl_g,
    bf16* __restrict__ ctxh, bf16* __restrict__ ctxl)
{
    extern __shared__ bf16 sm[];
    const int t    = threadIdx.x;
    const int lane = t & 31;
    const int wid  = t >> 5;
    const int warp_m = wid >> 1;   // 0..3 (x32 q)
    const int warp_n = wid & 1;    // 0..1 (x32 d)
    const int bh = blockIdx.y;
    const int q0 = blockIdx.x * 128;

    const bf16* Ph = Ph_g + (size_t)bh * Sq * Sq;
    const bf16* Pl = Pl_g + (size_t)bh * Sq * Sq;
    const bf16* Vh = Vh_g + (size_t)bh * Sq * DKq;
    const bf16* Vl = Vl_g + (size_t)bh * Sq * DKq;

    float acc[2][4][4];
#pragma unroll
    for (int i = 0; i < 2; i++)
#pragma unroll
        for (int j = 0; j < 4; j++)
#pragma unroll
            for (int r = 0; r < 4; r++) acc[i][j][r] = 0.f;

    const unsigned s0 = smaddr(sm);
    const int nk = Sq / 32;   // 64

    av_load(s0, Ph, Pl, Vh, Vl, q0, 0, t);
    CPCOMMIT;

    for (int i = 0; i < nk; i++) {
        CPWAIT0;
        __syncthreads();
        if (i + 1 < nk) {
            av_load(s0 + ((i+1)&1)*AV_STAGE_H*2, Ph, Pl, Vh, Vl, q0, (i+1)*32, t);
            CPCOMMIT;
        }
        unsigned sb = s0 + (i&1)*AV_STAGE_H*2;

#pragma unroll
        for (int k16 = 0; k16 < 32; k16 += 16) {
            unsigned ah[2][4], al[2][4], bh[4][2], bl[4][2];
            int arow = warp_m*32 + (lane & 15);
            int acol = k16 + ((lane >> 4) << 3);
#pragma unroll
            for (int mt = 0; mt < 2; mt++) {
                unsigned ad = sb + (unsigned)((arow + mt*16)*40 + acol)*2;
                LDSM4(ah[mt][0], ah[mt][1], ah[mt][2], ah[mt][3], ad);
                LDSM4(al[mt][0], al[mt][1], al[mt][2], al[mt][3], ad + 5120*2);
            }
            int vrow = k16 + (lane & 15);
            int vcb  = warp_n*32 + ((lane >> 4) << 3);
#pragma unroll
            for (int pr = 0; pr < 2; pr++) {
                unsigned bd = sb + 10240*2 + (unsigned)(vrow*72 + vcb + pr*16)*2;
                unsigned r0, r1, r2, r3;
                LDSM4T(r0, r1, r2, r3, bd);
                bh[pr*2][0] = r0; bh[pr*2][1] = r1;
                bh[pr*2+1][0] = r2; bh[pr*2+1][1] = r3;
                LDSM4T(r0, r1, r2, r3, bd + 2304*2);
                bl[pr*2][0] = r0; bl[pr*2][1] = r1;
                bl[pr*2+1][0] = r2; bl[pr*2+1][1] = r3;
            }
#pragma unroll
            for (int mt = 0; mt < 2; mt++)
#pragma unroll
                for (int nt = 0; nt < 4; nt++) {
                    MMA16816(acc[mt][nt], ah[mt], bh[nt]);
                    MMA16816(acc[mt][nt], ah[mt], bl[nt]);
                    MMA16816(acc[mt][nt], al[mt], bh[nt]);
                }
        }
    }

    const int b = bh >> 4, h = bh & 15;
#pragma unroll
    for (int mt = 0; mt < 2; mt++)
#pragma unroll
        for (int nt = 0; nt < 4; nt++) {
            int q = q0 + warp_m*32 + mt*16 + (lane >> 2);
            int d = warp_n*32 + nt*8 + ((lane & 3) << 1);
            size_t idx = ((size_t)(b*Sq + q))*Dm + h*DKq + d;
            split2(acc[mt][nt][0], acc[mt][nt][1], ctxh + idx, ctxl + idx);
            split2(acc[mt][nt][2], acc[mt][nt][3],
                   ctxh + idx + (size_t)8*Dm, ctxl + idx + (size_t)8*Dm);
        }
}

// ---------------------------------------------------------------------------
extern "C" void kernel_launch(void* const* d_in, const int* in_sizes, int n_in,
                              void* d_out, int out_size)
{
    const float* x  = (const float*)d_in[0];
    const float* Wq = (const float*)d_in[1];
    const float* bq = (const float*)d_in[2];
    const float* Wk = (const float*)d_in[3];
    const float* bk = (const float*)d_in[4];
    const float* Wv = (const float*)d_in[5];
    const float* bv = (const float*)d_in[6];
    const float* Wo = (const float*)d_in[7];
    const float* bo = (const float*)d_in[8];

    float* out  = (float*)d_out;
    float* attn = out + (size_t)NROWS * Dm;

    bf16 *xh, *xl, *wh, *wl, *qh, *ql, *kh, *kl, *vh, *vl, *ph, *pl, *ch, *cl;
    cudaGetSymbolAddress((void**)&xh, g_xh); cudaGetSymbolAddress((void**)&xl, g_xl);
    cudaGetSymbolAddress((void**)&wh, g_wh); cudaGetSymbolAddress((void**)&wl, g_wl);
    cudaGetSymbolAddress((void**)&qh, g_qh); cudaGetSymbolAddress((void**)&ql, g_ql);
    cudaGetSymbolAddress((void**)&kh, g_kh); cudaGetSymbolAddress((void**)&kl, g_kl);
    cudaGetSymbolAddress((void**)&vh, g_vh); cudaGetSymbolAddress((void**)&vl, g_vl);
    cudaGetSymbolAddress((void**)&ph, g_ph); cudaGetSymbolAddress((void**)&pl, g_pl);
    cudaGetSymbolAddress((void**)&ch, g_ch); cudaGetSymbolAddress((void**)&cl, g_cl);

    const int ntSmem = 2 * NT_STAGE_H * 2;   // 81920 B
    const int avSmem = 2 * AV_STAGE_H * 2;   // 59392 B
    cudaFuncSetAttribute(gemm_bf16x2_nt, cudaFuncAttributeMaxDynamicSharedMemorySize, ntSmem);
    cudaFuncSetAttribute(av_bf16x2,      cudaFuncAttributeMaxDynamicSharedMemorySize, avSmem);

    // 1. split inputs into bf16 hi/lo
    split_kernel<<<(NROWS*Dm/4 + 255)/256, 256>>>(x, xh, xl, NROWS*Dm/4);
    const int wq4 = Dm*Dm/4;
    split_kernel<<<(wq4+255)/256, 256>>>(Wq, wh,          wl,          wq4);
    split_kernel<<<(wq4+255)/256, 256>>>(Wk, wh + Dm*Dm,  wl + Dm*Dm,  wq4);
    split_kernel<<<(wq4+255)/256, 256>>>(Wv, wh + 2*Dm*Dm, wl + 2*Dm*Dm, wq4);
    split_kernel<<<(wq4+255)/256, 256>>>(Wo, wh + 3*Dm*Dm, wl + 3*Dm*Dm, wq4);

    // 2. Q/K/V projections (mode 0: head-split bf16 hi/lo out)
    dim3 gProj(Dm/128, NROWS/128, 1);    // (8, 32)
    gemm_bf16x2_nt<<<gProj, 256, ntSmem>>>(xh, xl, Dm, 0, wh,          wl,          Dm, 0,
                                           bq, nullptr, 0, 0, qh, ql, Dm, 1.f, 0);
    gemm_bf16x2_nt<<<gProj, 256, ntSmem>>>(xh, xl, Dm, 0, wh + Dm*Dm,  wl + Dm*Dm,  Dm, 0,
                                           bk, nullptr, 0, 0, kh, kl, Dm, 1.f, 0);
    gemm_bf16x2_nt<<<gProj, 256, ntSmem>>>(xh, xl, Dm, 0, wh + 2*Dm*Dm, wl + 2*Dm*Dm, Dm, 0,
                                           bv, nullptr, 0, 0, vh, vl, Dm, 1.f, 0);

    // 3. scores = 0.125 * Q K^T  (per-head NT GEMM, fp32 out to attn)
    dim3 gSc(Sq/128, Sq/128, BH);        // (16, 16, 32)
    gemm_bf16x2_nt<<<gSc, 256, ntSmem>>>(qh, ql, DKq, (long long)Sq*DKq,
                                         kh, kl, DKq, (long long)Sq*DKq,
                                         nullptr, attn, (long long)Sq*Sq, Sq,
                                         nullptr, nullptr, DKq, 0.125f, 1);

    // 4. softmax (fp32, in place) + bf16 hi/lo split of P
    softmax_split<<<BH*Sq, 256>>>(attn, ph, pl);

    // 5. ctx = P V (bf16 hi/lo out)
    dim3 gAV(Sq/128, BH);                // (16, 32)
    av_bf16x2<<<gAV, 256, avSmem>>>(ph, pl, vh, vl, ch, cl);

    // 6. output projection (mode 1: fp32 out + bias)
    gemm_bf16x2_nt<<<gProj, 256, ntSmem>>>(ch, cl, Dm, 0, wh + 3*Dm*Dm, wl + 3*Dm*Dm, Dm, 0,
                                           bo, out, 0, Dm, nullptr, nullptr, Dm, 1.f, 1);
}

// round 4
// speedup vs baseline: 2.7137x; 1.2259x over previous
#include <cuda_runtime.h>
#include <cuda_bf16.h>

#define Bq 2
#define Sq 2048
#define Dm 1024
#define Hh 16
#define DKq 64
#define NROWS (Bq*Sq)      // 4096
#define BH (Bq*Hh)         // 32

typedef __nv_bfloat16 bf16;
typedef __nv_bfloat162 bf162;

// -------- device scratch (allocation-free rule: __device__ globals) ---------
__device__ bf16 g_xh[NROWS*Dm], g_xl[NROWS*Dm];
__device__ bf16 g_wh[4*Dm*Dm],  g_wl[4*Dm*Dm];
__device__ bf16 g_qh[BH*Sq*DKq], g_ql[BH*Sq*DKq];
__device__ bf16 g_kh[BH*Sq*DKq], g_kl[BH*Sq*DKq];
__device__ bf16 g_vh[BH*Sq*DKq], g_vl[BH*Sq*DKq];
__device__ bf16 g_ch[NROWS*Dm], g_cl[NROWS*Dm];
__device__ float2 g_ml[BH*Sq];          // per-row {max, 1/sum}

// ------------------------------- PTX helpers --------------------------------
#define LDSM4(r0,r1,r2,r3,addr) \
    asm volatile("ldmatrix.sync.aligned.m8n8.x4.shared.b16 {%0,%1,%2,%3},[%4];" \
                 : "=r"(r0),"=r"(r1),"=r"(r2),"=r"(r3) : "r"(addr))
#define LDSM4T(r0,r1,r2,r3,addr) \
    asm volatile("ldmatrix.sync.aligned.m8n8.x4.trans.shared.b16 {%0,%1,%2,%3},[%4];" \
                 : "=r"(r0),"=r"(r1),"=r"(r2),"=r"(r3) : "r"(addr))
#define MMA16816(ac,a,b) \
    asm volatile("mma.sync.aligned.m16n8k16.row.col.f32.bf16.bf16.f32 " \
                 "{%0,%1,%2,%3},{%4,%5,%6,%7},{%8,%9},{%0,%1,%2,%3};" \
                 : "+f"((ac)[0]),"+f"((ac)[1]),"+f"((ac)[2]),"+f"((ac)[3]) \
                 : "r"((a)[0]),"r"((a)[1]),"r"((a)[2]),"r"((a)[3]), \
                   "r"((b)[0]),"r"((b)[1]))
#define CPASYNC16(dst,src) \
    asm volatile("cp.async.cg.shared.global [%0],[%1],16;" \
                 :: "r"(dst), "l"(__cvta_generic_to_global((const void*)(src))))
#define CPCOMMIT asm volatile("cp.async.commit_group;")
#define CPWAIT0  asm volatile("cp.async.wait_group 0;")

__device__ __forceinline__ unsigned smaddr(const void* p) {
    return (unsigned)__cvta_generic_to_shared(p);
}

__device__ __forceinline__ unsigned pack_bf16x2(float hi, float lo) {
    unsigned r;
    asm("cvt.rn.bf16x2.f32 %0, %1, %2;" : "=r"(r) : "f"(hi), "f"(lo));
    return r;   // lo16 = bf16(lo), hi16 = bf16(hi)
}

__device__ __forceinline__ void split2(float x, float y, bf16* hp, bf16* lp) {
    unsigned h = pack_bf16x2(y, x);
    float rx = x - __uint_as_float(h << 16);
    float ry = y - __uint_as_float(h & 0xffff0000u);
    unsigned l = pack_bf16x2(ry, rx);
    *(unsigned*)hp = h;
    *(unsigned*)lp = l;
}

// ------------------------------- split kernel -------------------------------
__global__ __launch_bounds__(256) void split_kernel(
    const float* __restrict__ src, bf16* __restrict__ hi, bf16* __restrict__ lo, int n4)
{
    int i = blockIdx.x * blockDim.x + threadIdx.x;
    if (i >= n4) return;
    float4 v = ((const float4*)src)[i];
    split2(v.x, v.y, hi + (size_t)i*4,     lo + (size_t)i*4);
    split2(v.z, v.w, hi + (size_t)i*4 + 2, lo + (size_t)i*4 + 2);
}

// ---------------------------------------------------------------------------
// Generic NT GEMM on hi/lo bf16 pairs (projections): unchanged from R2.
// ---------------------------------------------------------------------------
#define NT_STAGE_H 20480

__device__ __forceinline__ void nt_load(
    unsigned sb,
    const bf16* __restrict__ Ah, const bf16* __restrict__ Al,
    const bf16* __restrict__ Wh, const bf16* __restrict__ Wl,
    int lda, int ldw, int m0, int n0, int kt, int t)
{
#pragma unroll
    for (int j = 0; j < 2; j++) {
        int idx = t + j*256;
        int row = idx >> 2;
        int q   = (idx & 3) * 8;
        unsigned so = (unsigned)(row*40 + q) * 2;
        CPASYNC16(sb + so,               Ah + (size_t)(m0+row)*lda + kt + q);
        CPASYNC16(sb + 5120*2  + so,     Al + (size_t)(m0+row)*lda + kt + q);
        CPASYNC16(sb + 10240*2 + so,     Wh + (size_t)(n0+row)*ldw + kt + q);
        CPASYNC16(sb + 15360*2 + so,     Wl + (size_t)(n0+row)*ldw + kt + q);
    }
}

__global__ __launch_bounds__(256) void gemm_bf16x2_nt(
    const bf16* __restrict__ Ah, const bf16* __restrict__ Al, int lda,
    const bf16* __restrict__ Wh, const bf16* __restrict__ Wl, int ldw,
    const float* __restrict__ bias,
    float* __restrict__ outF, int ldc,
    bf16* __restrict__ outHi, bf16* __restrict__ outLo,
    int K, int mode)
{
    extern __shared__ bf16 sm[];
    const int t    = threadIdx.x;
    const int lane = t & 31;
    const int wid  = t >> 5;
    const int warp_m = wid >> 2;
    const int warp_n = wid & 3;
    const int m0 = blockIdx.y * 128;
    const int n0 = blockIdx.x * 128;

    float acc[4][4][4];
#pragma unroll
    for (int i = 0; i < 4; i++)
#pragma unroll
        for (int j = 0; j < 4; j++)
#pragma unroll
            for (int r = 0; r < 4; r++) acc[i][j][r] = 0.f;

    const unsigned s0 = smaddr(sm);
    const int nk = K / 32;

    nt_load(s0, Ah, Al, Wh, Wl, lda, ldw, m0, n0, 0, t);
    CPCOMMIT;

    for (int i = 0; i < nk; i++) {
        CPWAIT0;
        __syncthreads();
        if (i + 1 < nk) {
            nt_load(s0 + ((i+1)&1)*NT_STAGE_H*2, Ah, Al, Wh, Wl, lda, ldw,
                    m0, n0, (i+1)*32, t);
            CPCOMMIT;
        }
        unsigned sb = s0 + (i&1)*NT_STAGE_H*2;

#pragma unroll
        for (int k16 = 0; k16 < 32; k16 += 16) {
            unsigned ah[4][4], al[4][4], bh[4][2], bl[4][2];
            int arow = warp_m*64 + (lane & 15);
            int acol = k16 + ((lane >> 4) << 3);
#pragma unroll
            for (int mt = 0; mt < 4; mt++) {
                unsigned ad = sb + (unsigned)((arow + mt*16)*40 + acol)*2;
                LDSM4(ah[mt][0], ah[mt][1], ah[mt][2], ah[mt][3], ad);
                LDSM4(al[mt][0], al[mt][1], al[mt][2], al[mt][3], ad + 5120*2);
            }
            int brow = warp_n*32 + ((lane >> 4) << 3) + (lane & 7);
            int bcol = k16 + (((lane >> 3) & 1) << 3);
#pragma unroll
            for (int pr = 0; pr < 2; pr++) {
                unsigned bd = sb + 10240*2 + (unsigned)((brow + pr*16)*40 + bcol)*2;
                unsigned r0, r1, r2, r3;
                LDSM4(r0, r1, r2, r3, bd);
                bh[pr*2][0] = r0; bh[pr*2][1] = r1;
                bh[pr*2+1][0] = r2; bh[pr*2+1][1] = r3;
                LDSM4(r0, r1, r2, r3, bd + 5120*2);
                bl[pr*2][0] = r0; bl[pr*2][1] = r1;
                bl[pr*2+1][0] = r2; bl[pr*2+1][1] = r3;
            }
#pragma unroll
            for (int mt = 0; mt < 4; mt++)
#pragma unroll
                for (int nt = 0; nt < 4; nt++) {
                    MMA16816(acc[mt][nt], ah[mt], bh[nt]);
                    MMA16816(acc[mt][nt], ah[mt], bl[nt]);
                    MMA16816(acc[mt][nt], al[mt], bh[nt]);
                }
        }
    }

#pragma unroll
    for (int mt = 0; mt < 4; mt++)
#pragma unroll
        for (int nt = 0; nt < 4; nt++) {
            int r = m0 + warp_m*64 + mt*16 + (lane >> 2);
            int c = n0 + warp_n*32 + nt*8 + ((lane & 3) << 1);
            float v00 = acc[mt][nt][0] + bias[c];
            float v01 = acc[mt][nt][1] + bias[c+1];
            float v10 = acc[mt][nt][2] + bias[c];
            float v11 = acc[mt][nt][3] + bias[c+1];
            if (mode == 1) {
                *(float2*)&outF[(size_t)r*ldc + c]     = make_float2(v00, v01);
                *(float2*)&outF[(size_t)(r+8)*ldc + c] = make_float2(v10, v11);
            } else {
                int b = r >> 11, s = r & 2047;
                int h = c >> 6,  dk = c & 63;
                size_t base = (((size_t)(b*Hh + h))*Sq + s)*DKq + dk;
                split2(v00, v01, outHi + base, outLo + base);
                split2(v10, v11, outHi + base + 8*DKq, outLo + base + 8*DKq);
            }
        }
}

// ---------------------------------------------------------------------------
// Fused attention, two passes.
// Block: 128 q-rows, 8 warps x 16 rows. K-tile = 64 seq rows.
// SMEM (halves): Q hi/lo (2x9216), K double-buffered hi/lo (2x9216),
//                [pass2] V double-buffered hi/lo (2x9216). Stride 72.
// ---------------------------------------------------------------------------
#define KT 64
#define KV_BUF_H 9216      // halves per K (or V) buffer: hi(4608)+lo(4608)
#define Q_H 9216           // halves per Q matrix (128*72)

__device__ __forceinline__ void load_kv_tile(
    unsigned dsth, const bf16* __restrict__ gh, const bf16* __restrict__ gl,
    int row0, int t)
{
#pragma unroll
    for (int j = 0; j < 2; j++) {
        int c = t + j*256;
        int row = c >> 3, q = (c & 7)*8;
        unsigned so = (unsigned)(row*72 + q)*2;
        CPASYNC16(dsth + so,          gh + (size_t)(row0+row)*DKq + q);
        CPASYNC16(dsth + 4608*2 + so, gl + (size_t)(row0+row)*DKq + q);
    }
}

__device__ __forceinline__ void load_q_frags(
    unsigned qb, unsigned qfh[4][4], unsigned qfl[4][4], int warp, int lane)
{
    int arow = warp*16 + (lane & 15);
#pragma unroll
    for (int f = 0; f < 4; f++) {
        unsigned ad = qb + (unsigned)(arow*72 + f*16 + ((lane >> 4) << 3))*2;
        LDSM4(qfh[f][0], qfh[f][1], qfh[f][2], qfh[f][3], ad);
        LDSM4(qfl[f][0], qfl[f][1], qfl[f][2], qfl[f][3], ad + Q_H*2);
    }
}

// S tile: warp computes 16 q-rows x 64 k-cols. Identical in both passes.
__device__ __forceinline__ void compute_s(
    float s[8][4], const unsigned qfh[4][4], const unsigned qfl[4][4],
    unsigned kbuf, int lane)
{
#pragma unroll
    for (int j = 0; j < 8; j++)
#pragma unroll
        for (int r = 0; r < 4; r++) s[j][r] = 0.f;

    const int rbase = ((lane >> 4) << 3) + (lane & 7);
#pragma unroll
    for (int f = 0; f < 4; f++) {
        const int cbase = f*16 + (((lane >> 3) & 1) << 3);
#pragma unroll
        for (int pr = 0; pr < 4; pr++) {
            unsigned off = (unsigned)((pr*16 + rbase)*72 + cbase)*2;
            unsigned h0,h1,h2,h3, l0,l1,l2,l3;
            LDSM4(h0,h1,h2,h3, kbuf + off);
            LDSM4(l0,l1,l2,l3, kbuf + 4608*2 + off);
            unsigned bh0[2]={h0,h1}, bh1[2]={h2,h3};
            unsigned bl0[2]={l0,l1}, bl1[2]={l2,l3};
            MMA16816(s[2*pr],   qfh[f], bh0);
            MMA16816(s[2*pr],   qfh[f], bl0);
            MMA16816(s[2*pr],   qfl[f], bh0);
            MMA16816(s[2*pr+1], qfh[f], bh1);
            MMA16816(s[2*pr+1], qfh[f], bl1);
            MMA16816(s[2*pr+1], qfl[f], bh1);
        }
    }
#pragma unroll
    for (int j = 0; j < 8; j++)
#pragma unroll
        for (int r = 0; r < 4; r++) s[j][r] *= 0.125f;
}

__global__ __launch_bounds__(256) void attn_pass1(
    const bf16* __restrict__ qh_g, const bf16* __restrict__ ql_g,
    const bf16* __restrict__ kh_g, const bf16* __restrict__ kl_g,
    float2* __restrict__ ml)
{
    extern __shared__ bf16 sm[];
    const int t = threadIdx.x, lane = t & 31, warp = t >> 5;
    const int bh = blockIdx.y, q0 = blockIdx.x * 128;
    const bf16* Qh = qh_g + (size_t)bh*Sq*DKq;
    const bf16* Ql = ql_g + (size_t)bh*Sq*DKq;
    const bf16* Kh = kh_g + (size_t)bh*Sq*DKq;
    const bf16* Kl = kl_g + (size_t)bh*Sq*DKq;

    const unsigned s0 = smaddr(sm);
    const unsigned qb = s0;
    const unsigned kb = s0 + 2*Q_H*2;

    // load Q (128x64 hi/lo)
#pragma unroll
    for (int j = 0; j < 4; j++) {
        int c = t + j*256;
        int row = c >> 3, q = (c & 7)*8;
        unsigned so = (unsigned)(row*72 + q)*2;
        CPASYNC16(qb + so,         Qh + (size_t)(q0+row)*DKq + q);
        CPASYNC16(qb + Q_H*2 + so, Ql + (size_t)(q0+row)*DKq + q);
    }
    load_kv_tile(kb, Kh, Kl, 0, t);
    CPCOMMIT;
    CPWAIT0;
    __syncthreads();

    unsigned qfh[4][4], qfl[4][4];
    load_q_frags(qb, qfh, qfl, warp, lane);

    float m0 = -1e30f, m1 = -1e30f, l0v = 0.f, l1v = 0.f;
    const int nk = Sq / KT;   // 32

    for (int i = 0; i < nk; i++) {
        if (i > 0) { CPWAIT0; __syncthreads(); }
        if (i + 1 < nk) {
            load_kv_tile(kb + ((i+1)&1)*KV_BUF_H*2, Kh, Kl, (i+1)*KT, t);
            CPCOMMIT;
        }
        float s[8][4];
        compute_s(s, qfh, qfl, kb + (i&1)*KV_BUF_H*2, lane);

        float tm0 = -1e30f, tm1 = -1e30f;
#pragma unroll
        for (int j = 0; j < 8; j++) {
            tm0 = fmaxf(tm0, fmaxf(s[j][0], s[j][1]));
            tm1 = fmaxf(tm1, fmaxf(s[j][2], s[j][3]));
        }
        tm0 = fmaxf(tm0, __shfl_xor_sync(0xffffffffu, tm0, 1));
        tm0 = fmaxf(tm0, __shfl_xor_sync(0xffffffffu, tm0, 2));
        tm1 = fmaxf(tm1, __shfl_xor_sync(0xffffffffu, tm1, 1));
        tm1 = fmaxf(tm1, __shfl_xor_sync(0xffffffffu, tm1, 2));

        float nm0 = fmaxf(m0, tm0), nm1 = fmaxf(m1, tm1);
        float c0 = __expf(m0 - nm0), c1 = __expf(m1 - nm1);
        float ts0 = 0.f, ts1 = 0.f;
#pragma unroll
        for (int j = 0; j < 8; j++) {
            ts0 += __expf(s[j][0] - nm0) + __expf(s[j][1] - nm0);
            ts1 += __expf(s[j][2] - nm1) + __expf(s[j][3] - nm1);
        }
        ts0 += __shfl_xor_sync(0xffffffffu, ts0, 1);
        ts0 += __shfl_xor_sync(0xffffffffu, ts0, 2);
        ts1 += __shfl_xor_sync(0xffffffffu, ts1, 1);
        ts1 += __shfl_xor_sync(0xffffffffu, ts1, 2);

        l0v = l0v*c0 + ts0;  m0 = nm0;
        l1v = l1v*c1 + ts1;  m1 = nm1;
        __syncthreads();
    }

    if ((lane & 3) == 0) {
        int r = q0 + warp*16 + (lane >> 2);
        ml[(size_t)bh*Sq + r]     = make_float2(m0, 1.0f/l0v);
        ml[(size_t)bh*Sq + r + 8] = make_float2(m1, 1.0f/l1v);
    }
}

__global__ __launch_bounds__(256) void attn_pass2(
    const bf16* __restrict__ qh_g, const bf16* __restrict__ ql_g,
    const bf16* __restrict__ kh_g, const bf16* __restrict__ kl_g,
    const bf16* __restrict__ vh_g, const bf16* __restrict__ vl_g,
    const float2* __restrict__ ml, float* __restrict__ attn,
    bf16* __restrict__ ctxh, bf16* __restrict__ ctxl)
{
    extern __shared__ bf16 sm[];
    const int t = threadIdx.x, lane = t & 31, warp = t >> 5;
    const int bh = blockIdx.y, q0 = blockIdx.x * 128;
    const bf16* Qh = qh_g + (size_t)bh*Sq*DKq;
    const bf16* Ql = ql_g + (size_t)bh*Sq*DKq;
    const bf16* Kh = kh_g + (size_t)bh*Sq*DKq;
    const bf16* Kl = kl_g + (size_t)bh*Sq*DKq;
    const bf16* Vh = vh_g + (size_t)bh*Sq*DKq;
    const bf16* Vl = vl_g + (size_t)bh*Sq*DKq;

    const unsigned s0 = smaddr(sm);
    const unsigned qb = s0;
    const unsigned kb = s0 + 2*Q_H*2;
    const unsigned vb = kb + 2*KV_BUF_H*2;

#pragma unroll
    for (int j = 0; j < 4; j++) {
        int c = t + j*256;
        int row = c >> 3, q = (c & 7)*8;
        unsigned so = (unsigned)(row*72 + q)*2;
        CPASYNC16(qb + so,         Qh + (size_t)(q0+row)*DKq + q);
        CPASYNC16(qb + Q_H*2 + so, Ql + (size_t)(q0+row)*DKq + q);
    }
    load_kv_tile(kb, Kh, Kl, 0, t);
    load_kv_tile(vb, Vh, Vl, 0, t);
    CPCOMMIT;
    CPWAIT0;
    __syncthreads();

    unsigned qfh[4][4], qfl[4][4];
    load_q_frags(qb, qfh, qfl, warp, lane);

    const int g = lane >> 2;
    const int r0 = q0 + warp*16 + g;
    float2 ml0 = ml[(size_t)bh*Sq + r0];
    float2 ml1 = ml[(size_t)bh*Sq + r0 + 8];
    const float mm0 = ml0.x, il0 = ml0.y, mm1 = ml1.x, il1 = ml1.y;

    float* aptr0 = attn + ((size_t)bh*Sq + r0)*Sq + 2*(lane & 3);
    float* aptr1 = aptr0 + (size_t)8*Sq;

    float ctx[8][4];
#pragma unroll
    for (int j = 0; j < 8; j++)
#pragma unroll
        for (int r = 0; r < 4; r++) ctx[j][r] = 0.f;

    const int nk = Sq / KT;

    for (int i = 0; i < nk; i++) {
        if (i > 0) { CPWAIT0; __syncthreads(); }
        if (i + 1 < nk) {
            load_kv_tile(kb + ((i+1)&1)*KV_BUF_H*2, Kh, Kl, (i+1)*KT, t);
            load_kv_tile(vb + ((i+1)&1)*KV_BUF_H*2, Vh, Vl, (i+1)*KT, t);
            CPCOMMIT;
        }
        float s[8][4];
        compute_s(s, qfh, qfl, kb + (i&1)*KV_BUF_H*2, lane);

        const int k0 = i*KT;
#pragma unroll
        for (int j = 0; j < 8; j++) {
            float p0 = __expf(s[j][0] - mm0) * il0;
            float p1 = __expf(s[j][1] - mm0) * il0;
            float p2 = __expf(s[j][2] - mm1) * il1;
            float p3 = __expf(s[j][3] - mm1) * il1;
            *(float2*)(aptr0 + k0 + 8*j) = make_float2(p0, p1);
            *(float2*)(aptr1 + k0 + 8*j) = make_float2(p2, p3);
            s[j][0] = p0; s[j][1] = p1; s[j][2] = p2; s[j][3] = p3;
        }

        // PV: A = P fragments straight from registers (hi + residual lo)
        const unsigned vbuf = vb + (i&1)*KV_BUF_H*2;
#pragma unroll
        for (int f = 0; f < 4; f++) {
            unsigned pah[4], pal[4];
#pragma unroll
            for (int u = 0; u < 2; u++) {
                const float* pv = s[2*f + u];
                unsigned h0 = pack_bf16x2(pv[1], pv[0]);
                float e0 = pv[0] - __uint_as_float(h0 << 16);
                float e1 = pv[1] - __uint_as_float(h0 & 0xffff0000u);
                pal[2*u]   = pack_bf16x2(e1, e0);
                pah[2*u]   = h0;
                unsigned h1 = pack_bf16x2(pv[3], pv[2]);
                float e2 = pv[2] - __uint_as_float(h1 << 16);
                float e3 = pv[3] - __uint_as_float(h1 & 0xffff0000u);
                pal[2*u+1] = pack_bf16x2(e3, e2);
                pah[2*u+1] = h1;
            }
            // reorder: A frag = {a0,a1,a2,a3} with a0,a1 from u=0, a2,a3 from u=1
            unsigned pahf[4] = {pah[0], pah[1], pah[2], pah[3]};
            unsigned palf[4] = {pal[0], pal[1], pal[2], pal[3]};

#pragma unroll
            for (int pr = 0; pr < 4; pr++) {
                unsigned off = (unsigned)((f*16 + (lane & 15))*72
                               + pr*16 + ((lane >> 4) << 3))*2;
                unsigned h0,h1,h2,h3, l0,l1,l2,l3;
                LDSM4T(h0,h1,h2,h3, vbuf + off);
                LDSM4T(l0,l1,l2,l3, vbuf + 4608*2 + off);
                unsigned bh0[2]={h0,h1}, bh1[2]={h2,h3};
                unsigned bl0[2]={l0,l1}, bl1[2]={l2,l3};
                MMA16816(ctx[2*pr],   pahf, bh0);
                MMA16816(ctx[2*pr],   pahf, bl0);
                MMA16816(ctx[2*pr],   palf, bh0);
                MMA16816(ctx[2*pr+1], pahf, bh1);
                MMA16816(ctx[2*pr+1], pahf, bl1);
                MMA16816(ctx[2*pr+1], palf, bh1);
            }
        }
        __syncthreads();
    }

    const int b = bh >> 4, hidx = bh & 15;
#pragma unroll
    for (int j = 0; j < 8; j++) {
        int d = hidx*DKq + 8*j + 2*(lane & 3);
        size_t idx0 = ((size_t)(b*Sq + r0))*Dm + d;
        split2(ctx[j][0], ctx[j][1], ctxh + idx0, ctxl + idx0);
        size_t idx1 = idx0 + (size_t)8*Dm;
        split2(ctx[j][2], ctx[j][3], ctxh + idx1, ctxl + idx1);
    }
}

// ---------------------------------------------------------------------------
extern "C" void kernel_launch(void* const* d_in, const int* in_sizes, int n_in,
                              void* d_out, int out_size)
{
    const float* x  = (const float*)d_in[0];
    const float* Wq = (const float*)d_in[1];
    const float* bq = (const float*)d_in[2];
    const float* Wk = (const float*)d_in[3];
    const float* bk = (const float*)d_in[4];
    const float* Wv = (const float*)d_in[5];
    const float* bv = (const float*)d_in[6];
    const float* Wo = (const float*)d_in[7];
    const float* bo = (const float*)d_in[8];

    float* out  = (float*)d_out;
    float* attn = out + (size_t)NROWS * Dm;

    bf16 *xh, *xl, *wh, *wl, *qh, *ql, *kh, *kl, *vh, *vl, *ch, *cl;
    float2* mlp;
    cudaGetSymbolAddress((void**)&xh, g_xh); cudaGetSymbolAddress((void**)&xl, g_xl);
    cudaGetSymbolAddress((void**)&wh, g_wh); cudaGetSymbolAddress((void**)&wl, g_wl);
    cudaGetSymbolAddress((void**)&qh, g_qh); cudaGetSymbolAddress((void**)&ql, g_ql);
    cudaGetSymbolAddress((void**)&kh, g_kh); cudaGetSymbolAddress((void**)&kl, g_kl);
    cudaGetSymbolAddress((void**)&vh, g_vh); cudaGetSymbolAddress((void**)&vl, g_vl);
    cudaGetSymbolAddress((void**)&ch, g_ch); cudaGetSymbolAddress((void**)&cl, g_cl);
    cudaGetSymbolAddress((void**)&mlp, g_ml);

    const int ntSmem = 2 * NT_STAGE_H * 2;                      // 81920 B
    const int p1Smem = (2*Q_H + 2*KV_BUF_H) * 2;                // 73728 B
    const int p2Smem = (2*Q_H + 4*KV_BUF_H) * 2;                // 110592 B
    cudaFuncSetAttribute(gemm_bf16x2_nt, cudaFuncAttributeMaxDynamicSharedMemorySize, ntSmem);
    cudaFuncSetAttribute(attn_pass1,     cudaFuncAttributeMaxDynamicSharedMemorySize, p1Smem);
    cudaFuncSetAttribute(attn_pass2,     cudaFuncAttributeMaxDynamicSharedMemorySize, p2Smem);

    // 1. split inputs into bf16 hi/lo
    split_kernel<<<(NROWS*Dm/4 + 255)/256, 256>>>(x, xh, xl, NROWS*Dm/4);
    const int wq4 = Dm*Dm/4;
    split_kernel<<<(wq4+255)/256, 256>>>(Wq, wh,           wl,           wq4);
    split_kernel<<<(wq4+255)/256, 256>>>(Wk, wh + Dm*Dm,   wl + Dm*Dm,   wq4);
    split_kernel<<<(wq4+255)/256, 256>>>(Wv, wh + 2*Dm*Dm, wl + 2*Dm*Dm, wq4);
    split_kernel<<<(wq4+255)/256, 256>>>(Wo, wh + 3*Dm*Dm, wl + 3*Dm*Dm, wq4);

    // 2. Q/K/V projections
    dim3 gProj(Dm/128, NROWS/128);
    gemm_bf16x2_nt<<<gProj, 256, ntSmem>>>(xh, xl, Dm, wh,           wl,           Dm,
                                           bq, nullptr, 0, qh, ql, Dm, 0);
    gemm_bf16x2_nt<<<gProj, 256, ntSmem>>>(xh, xl, Dm, wh + Dm*Dm,   wl + Dm*Dm,   Dm,
                                           bk, nullptr, 0, kh, kl, Dm, 0);
    gemm_bf16x2_nt<<<gProj, 256, ntSmem>>>(xh, xl, Dm, wh + 2*Dm*Dm, wl + 2*Dm*Dm, Dm,
                                           bv, nullptr, 0, vh, vl, Dm, 0);

    // 3. fused attention: pass1 (m, 1/l), pass2 (attn write + P·V)
    dim3 gAttn(Sq/128, BH);   // (16, 32)
    attn_pass1<<<gAttn, 256, p1Smem>>>(qh, ql, kh, kl, mlp);
    attn_pass2<<<gAttn, 256, p2Smem>>>(qh, ql, kh, kl, vh, vl, mlp, attn, ch, cl);

    // 4. output projection
    gemm_bf16x2_nt<<<gProj, 256, ntSmem>>>(ch, cl, Dm, wh + 3*Dm*Dm, wl + 3*Dm*Dm, Dm,
                                           bo, out, Dm, nullptr, nullptr, Dm, 1);
}

// round 5
// speedup vs baseline: 2.8150x; 1.0373x over previous
#include <cuda_runtime.h>
#include <cuda_bf16.h>

#define Bq 2
#define Sq 2048
#define Dm 1024
#define Hh 16
#define DKq 64
#define NROWS (Bq*Sq)      // 4096
#define BH (Bq*Hh)         // 32

typedef __nv_bfloat16 bf16;

// -------- device scratch (allocation-free rule: __device__ globals) ---------
__device__ bf16 g_xh[NROWS*Dm], g_xl[NROWS*Dm];
__device__ bf16 g_wh[4*Dm*Dm],  g_wl[4*Dm*Dm];
__device__ bf16 g_qh[BH*Sq*DKq], g_ql[BH*Sq*DKq];
__device__ bf16 g_kh[BH*Sq*DKq], g_kl[BH*Sq*DKq];
__device__ bf16 g_vh[BH*Sq*DKq], g_vl[BH*Sq*DKq];
__device__ bf16 g_ch[NROWS*Dm], g_cl[NROWS*Dm];
__device__ float g_invl[BH*Sq];         // per-row 1/sum

// ------------------------------- PTX helpers --------------------------------
#define LDSM4(r0,r1,r2,r3,addr) \
    asm volatile("ldmatrix.sync.aligned.m8n8.x4.shared.b16 {%0,%1,%2,%3},[%4];" \
                 : "=r"(r0),"=r"(r1),"=r"(r2),"=r"(r3) : "r"(addr))
#define LDSM4T(r0,r1,r2,r3,addr) \
    asm volatile("ldmatrix.sync.aligned.m8n8.x4.trans.shared.b16 {%0,%1,%2,%3},[%4];" \
                 : "=r"(r0),"=r"(r1),"=r"(r2),"=r"(r3) : "r"(addr))
#define MMA16816(ac,a,b) \
    asm volatile("mma.sync.aligned.m16n8k16.row.col.f32.bf16.bf16.f32 " \
                 "{%0,%1,%2,%3},{%4,%5,%6,%7},{%8,%9},{%0,%1,%2,%3};" \
                 : "+f"((ac)[0]),"+f"((ac)[1]),"+f"((ac)[2]),"+f"((ac)[3]) \
                 : "r"((a)[0]),"r"((a)[1]),"r"((a)[2]),"r"((a)[3]), \
                   "r"((b)[0]),"r"((b)[1]))
#define CPASYNC16(dst,src) \
    asm volatile("cp.async.cg.shared.global [%0],[%1],16;" \
                 :: "r"(dst), "l"(__cvta_generic_to_global((const void*)(src))))
#define CPCOMMIT asm volatile("cp.async.commit_group;")
#define CPWAIT0  asm volatile("cp.async.wait_group 0;")

__device__ __forceinline__ unsigned smaddr(const void* p) {
    return (unsigned)__cvta_generic_to_shared(p);
}

__device__ __forceinline__ float ex2(float x) {
    float r;
    asm("ex2.approx.f32 %0, %1;" : "=f"(r) : "f"(x));
    return r;
}

__device__ __forceinline__ unsigned pack_bf16x2(float hi, float lo) {
    unsigned r;
    asm("cvt.rn.bf16x2.f32 %0, %1, %2;" : "=r"(r) : "f"(hi), "f"(lo));
    return r;
}

__device__ __forceinline__ void split2(float x, float y, bf16* hp, bf16* lp) {
    unsigned h = pack_bf16x2(y, x);
    float rx = x - __uint_as_float(h << 16);
    float ry = y - __uint_as_float(h & 0xffff0000u);
    unsigned l = pack_bf16x2(ry, rx);
    *(unsigned*)hp = h;
    *(unsigned*)lp = l;
}

// ------------------------------- split kernel -------------------------------
__global__ __launch_bounds__(256) void split_kernel(
    const float* __restrict__ src, bf16* __restrict__ hi, bf16* __restrict__ lo, int n4)
{
    int i = blockIdx.x * blockDim.x + threadIdx.x;
    if (i >= n4) return;
    float4 v = ((const float4*)src)[i];
    split2(v.x, v.y, hi + (size_t)i*4,     lo + (size_t)i*4);
    split2(v.z, v.w, hi + (size_t)i*4 + 2, lo + (size_t)i*4 + 2);
}

// ---------------------------------------------------------------------------
// Generic NT GEMM on hi/lo bf16 pairs (projections).
// mode 0: head-split bf16 hi/lo out, value scaled by `scale` after bias.
// mode 1: fp32 rows out.
// ---------------------------------------------------------------------------
#define NT_STAGE_H 20480

__device__ __forceinline__ void nt_load(
    unsigned sb,
    const bf16* __restrict__ Ah, const bf16* __restrict__ Al,
    const bf16* __restrict__ Wh, const bf16* __restrict__ Wl,
    int lda, int ldw, int m0, int n0, int kt, int t)
{
#pragma unroll
    for (int j = 0; j < 2; j++) {
        int idx = t + j*256;
        int row = idx >> 2;
        int q   = (idx & 3) * 8;
        unsigned so = (unsigned)(row*40 + q) * 2;
        CPASYNC16(sb + so,               Ah + (size_t)(m0+row)*lda + kt + q);
        CPASYNC16(sb + 5120*2  + so,     Al + (size_t)(m0+row)*lda + kt + q);
        CPASYNC16(sb + 10240*2 + so,     Wh + (size_t)(n0+row)*ldw + kt + q);
        CPASYNC16(sb + 15360*2 + so,     Wl + (size_t)(n0+row)*ldw + kt + q);
    }
}

__global__ __launch_bounds__(256) void gemm_bf16x2_nt(
    const bf16* __restrict__ Ah, const bf16* __restrict__ Al, int lda,
    const bf16* __restrict__ Wh, const bf16* __restrict__ Wl, int ldw,
    const float* __restrict__ bias,
    float* __restrict__ outF, int ldc,
    bf16* __restrict__ outHi, bf16* __restrict__ outLo,
    int K, float scale, int mode)
{
    extern __shared__ bf16 sm[];
    const int t    = threadIdx.x;
    const int lane = t & 31;
    const int wid  = t >> 5;
    const int warp_m = wid >> 2;
    const int warp_n = wid & 3;
    const int m0 = blockIdx.y * 128;
    const int n0 = blockIdx.x * 128;

    float acc[4][4][4];
#pragma unroll
    for (int i = 0; i < 4; i++)
#pragma unroll
        for (int j = 0; j < 4; j++)
#pragma unroll
            for (int r = 0; r < 4; r++) acc[i][j][r] = 0.f;

    const unsigned s0 = smaddr(sm);
    const int nk = K / 32;

    nt_load(s0, Ah, Al, Wh, Wl, lda, ldw, m0, n0, 0, t);
    CPCOMMIT;

    for (int i = 0; i < nk; i++) {
        CPWAIT0;
        __syncthreads();
        if (i + 1 < nk) {
            nt_load(s0 + ((i+1)&1)*NT_STAGE_H*2, Ah, Al, Wh, Wl, lda, ldw,
                    m0, n0, (i+1)*32, t);
            CPCOMMIT;
        }
        unsigned sb = s0 + (i&1)*NT_STAGE_H*2;

#pragma unroll
        for (int k16 = 0; k16 < 32; k16 += 16) {
            unsigned ah[4][4], al[4][4], bh[4][2], bl[4][2];
            int arow = warp_m*64 + (lane & 15);
            int acol = k16 + ((lane >> 4) << 3);
#pragma unroll
            for (int mt = 0; mt < 4; mt++) {
                unsigned ad = sb + (unsigned)((arow + mt*16)*40 + acol)*2;
                LDSM4(ah[mt][0], ah[mt][1], ah[mt][2], ah[mt][3], ad);
                LDSM4(al[mt][0], al[mt][1], al[mt][2], al[mt][3], ad + 5120*2);
            }
            int brow = warp_n*32 + ((lane >> 4) << 3) + (lane & 7);
            int bcol = k16 + (((lane >> 3) & 1) << 3);
#pragma unroll
            for (int pr = 0; pr < 2; pr++) {
                unsigned bd = sb + 10240*2 + (unsigned)((brow + pr*16)*40 + bcol)*2;
                unsigned r0, r1, r2, r3;
                LDSM4(r0, r1, r2, r3, bd);
                bh[pr*2][0] = r0; bh[pr*2][1] = r1;
                bh[pr*2+1][0] = r2; bh[pr*2+1][1] = r3;
                LDSM4(r0, r1, r2, r3, bd + 5120*2);
                bl[pr*2][0] = r0; bl[pr*2][1] = r1;
                bl[pr*2+1][0] = r2; bl[pr*2+1][1] = r3;
            }
#pragma unroll
            for (int mt = 0; mt < 4; mt++)
#pragma unroll
                for (int nt = 0; nt < 4; nt++) {
                    MMA16816(acc[mt][nt], ah[mt], bh[nt]);
                    MMA16816(acc[mt][nt], ah[mt], bl[nt]);
                    MMA16816(acc[mt][nt], al[mt], bh[nt]);
                }
        }
    }

#pragma unroll
    for (int mt = 0; mt < 4; mt++)
#pragma unroll
        for (int nt = 0; nt < 4; nt++) {
            int r = m0 + warp_m*64 + mt*16 + (lane >> 2);
            int c = n0 + warp_n*32 + nt*8 + ((lane & 3) << 1);
            float v00 = acc[mt][nt][0] + bias[c];
            float v01 = acc[mt][nt][1] + bias[c+1];
            float v10 = acc[mt][nt][2] + bias[c];
            float v11 = acc[mt][nt][3] + bias[c+1];
            if (mode == 1) {
                *(float2*)&outF[(size_t)r*ldc + c]     = make_float2(v00, v01);
                *(float2*)&outF[(size_t)(r+8)*ldc + c] = make_float2(v10, v11);
            } else {
                v00 *= scale; v01 *= scale; v10 *= scale; v11 *= scale;
                int b = r >> 11, s = r & 2047;
                int h = c >> 6,  dk = c & 63;
                size_t base = (((size_t)(b*Hh + h))*Sq + s)*DKq + dk;
                split2(v00, v01, outHi + base, outLo + base);
                split2(v10, v11, outHi + base + 8*DKq, outLo + base + 8*DKq);
            }
        }
}

// ---------------------------------------------------------------------------
// Fused attention (single pass over K/V).
// Q pre-scaled by 0.125*log2(e): p = 2^(q.k) = exp(score).
// Writes UNNORMALIZED p to attn; accumulates l per row and ctx = sum p*V;
// ctx normalized in-register. Fixup kernel normalizes attn afterwards.
// ---------------------------------------------------------------------------
#define KT 64
#define KV_BUF_H 9216
#define Q_H 9216

__device__ __forceinline__ void load_kv_tile(
    unsigned dsth, const bf16* __restrict__ gh, const bf16* __restrict__ gl,
    int row0, int t)
{
#pragma unroll
    for (int j = 0; j < 2; j++) {
        int c = t + j*256;
        int row = c >> 3, q = (c & 7)*8;
        unsigned so = (unsigned)(row*72 + q)*2;
        CPASYNC16(dsth + so,          gh + (size_t)(row0+row)*DKq + q);
        CPASYNC16(dsth + 4608*2 + so, gl + (size_t)(row0+row)*DKq + q);
    }
}

__device__ __forceinline__ void compute_s(
    float s[8][4], const unsigned qfh[4][4], const unsigned qfl[4][4],
    unsigned kbuf, int lane)
{
#pragma unroll
    for (int j = 0; j < 8; j++)
#pragma unroll
        for (int r = 0; r < 4; r++) s[j][r] = 0.f;

    const int rbase = ((lane >> 4) << 3) + (lane & 7);
#pragma unroll
    for (int f = 0; f < 4; f++) {
        const int cbase = f*16 + (((lane >> 3) & 1) << 3);
#pragma unroll
        for (int pr = 0; pr < 4; pr++) {
            unsigned off = (unsigned)((pr*16 + rbase)*72 + cbase)*2;
            unsigned h0,h1,h2,h3, l0,l1,l2,l3;
            LDSM4(h0,h1,h2,h3, kbuf + off);
            LDSM4(l0,l1,l2,l3, kbuf + 4608*2 + off);
            unsigned bh0[2]={h0,h1}, bh1[2]={h2,h3};
            unsigned bl0[2]={l0,l1}, bl1[2]={l2,l3};
            MMA16816(s[2*pr],   qfh[f], bh0);
            MMA16816(s[2*pr],   qfh[f], bl0);
            MMA16816(s[2*pr],   qfl[f], bh0);
            MMA16816(s[2*pr+1], qfh[f], bh1);
            MMA16816(s[2*pr+1], qfh[f], bl1);
            MMA16816(s[2*pr+1], qfl[f], bh1);
        }
    }
}

__global__ __launch_bounds__(256) void attn_fused(
    const bf16* __restrict__ qh_g, const bf16* __restrict__ ql_g,
    const bf16* __restrict__ kh_g, const bf16* __restrict__ kl_g,
    const bf16* __restrict__ vh_g, const bf16* __restrict__ vl_g,
    float* __restrict__ attn, float* __restrict__ invl,
    bf16* __restrict__ ctxh, bf16* __restrict__ ctxl)
{
    extern __shared__ bf16 sm[];
    const int t = threadIdx.x, lane = t & 31, warp = t >> 5;
    const int bh = blockIdx.y, q0 = blockIdx.x * 128;
    const bf16* Qh = qh_g + (size_t)bh*Sq*DKq;
    const bf16* Ql = ql_g + (size_t)bh*Sq*DKq;
    const bf16* Kh = kh_g + (size_t)bh*Sq*DKq;
    const bf16* Kl = kl_g + (size_t)bh*Sq*DKq;
    const bf16* Vh = vh_g + (size_t)bh*Sq*DKq;
    const bf16* Vl = vl_g + (size_t)bh*Sq*DKq;

    const unsigned s0 = smaddr(sm);
    const unsigned qb = s0;
    const unsigned kb = s0 + 2*Q_H*2;
    const unsigned vb = kb + 2*KV_BUF_H*2;

#pragma unroll
    for (int j = 0; j < 4; j++) {
        int c = t + j*256;
        int row = c >> 3, q = (c & 7)*8;
        unsigned so = (unsigned)(row*72 + q)*2;
        CPASYNC16(qb + so,         Qh + (size_t)(q0+row)*DKq + q);
        CPASYNC16(qb + Q_H*2 + so, Ql + (size_t)(q0+row)*DKq + q);
    }
    load_kv_tile(kb, Kh, Kl, 0, t);
    load_kv_tile(vb, Vh, Vl, 0, t);
    CPCOMMIT;
    CPWAIT0;
    __syncthreads();

    unsigned qfh[4][4], qfl[4][4];
    {
        int arow = warp*16 + (lane & 15);
#pragma unroll
        for (int f = 0; f < 4; f++) {
            unsigned ad = qb + (unsigned)(arow*72 + f*16 + ((lane >> 4) << 3))*2;
            LDSM4(qfh[f][0], qfh[f][1], qfh[f][2], qfh[f][3], ad);
            LDSM4(qfl[f][0], qfl[f][1], qfl[f][2], qfl[f][3], ad + Q_H*2);
        }
    }

    const int g = lane >> 2;
    const int r0 = q0 + warp*16 + g;
    float* aptr0 = attn + ((size_t)bh*Sq + r0)*Sq + 2*(lane & 3);
    float* aptr1 = aptr0 + (size_t)8*Sq;

    float ctx[8][4];
#pragma unroll
    for (int j = 0; j < 8; j++)
#pragma unroll
        for (int r = 0; r < 4; r++) ctx[j][r] = 0.f;

    float l0v = 0.f, l1v = 0.f;    // per-thread partial row sums
    const int nk = Sq / KT;

    for (int i = 0; i < nk; i++) {
        if (i > 0) { CPWAIT0; __syncthreads(); }
        if (i + 1 < nk) {
            load_kv_tile(kb + ((i+1)&1)*KV_BUF_H*2, Kh, Kl, (i+1)*KT, t);
            load_kv_tile(vb + ((i+1)&1)*KV_BUF_H*2, Vh, Vl, (i+1)*KT, t);
            CPCOMMIT;
        }
        float s[8][4];
        compute_s(s, qfh, qfl, kb + (i&1)*KV_BUF_H*2, lane);

        const int k0 = i*KT;
#pragma unroll
        for (int j = 0; j < 8; j++) {
            float p0 = ex2(s[j][0]);
            float p1 = ex2(s[j][1]);
            float p2 = ex2(s[j][2]);
            float p3 = ex2(s[j][3]);
            *(float2*)(aptr0 + k0 + 8*j) = make_float2(p0, p1);
            *(float2*)(aptr1 + k0 + 8*j) = make_float2(p2, p3);
            l0v += p0 + p1;
            l1v += p2 + p3;
            s[j][0] = p0; s[j][1] = p1; s[j][2] = p2; s[j][3] = p3;
        }

        // PV: A-fragments straight from p registers (hi + residual lo)
        const unsigned vbuf = vb + (i&1)*KV_BUF_H*2;
#pragma unroll
        for (int f = 0; f < 4; f++) {
            unsigned pah[4], pal[4];
#pragma unroll
            for (int u = 0; u < 2; u++) {
                const float* pv = s[2*f + u];
                unsigned h0 = pack_bf16x2(pv[1], pv[0]);
                float e0 = pv[0] - __uint_as_float(h0 << 16);
                float e1 = pv[1] - __uint_as_float(h0 & 0xffff0000u);
                pal[2*u]   = pack_bf16x2(e1, e0);
                pah[2*u]   = h0;
                unsigned h1 = pack_bf16x2(pv[3], pv[2]);
                float e2 = pv[2] - __uint_as_float(h1 << 16);
                float e3 = pv[3] - __uint_as_float(h1 & 0xffff0000u);
                pal[2*u+1] = pack_bf16x2(e3, e2);
                pah[2*u+1] = h1;
            }
            unsigned pahf[4] = {pah[0], pah[1], pah[2], pah[3]};
            unsigned palf[4] = {pal[0], pal[1], pal[2], pal[3]};

#pragma unroll
            for (int pr = 0; pr < 4; pr++) {
                unsigned off = (unsigned)((f*16 + (lane & 15))*72
                               + pr*16 + ((lane >> 4) << 3))*2;
                unsigned h0,h1,h2,h3, l0,l1,l2,l3;
                LDSM4T(h0,h1,h2,h3, vbuf + off);
                LDSM4T(l0,l1,l2,l3, vbuf + 4608*2 + off);
                unsigned bh0[2]={h0,h1}, bh1[2]={h2,h3};
                unsigned bl0[2]={l0,l1}, bl1[2]={l2,l3};
                MMA16816(ctx[2*pr],   pahf, bh0);
                MMA16816(ctx[2*pr],   pahf, bl0);
                MMA16816(ctx[2*pr],   palf, bh0);
                MMA16816(ctx[2*pr+1], pahf, bh1);
                MMA16816(ctx[2*pr+1], pahf, bl1);
                MMA16816(ctx[2*pr+1], palf, bh1);
            }
        }
        __syncthreads();
    }

    // reduce row sums across the quad
    l0v += __shfl_xor_sync(0xffffffffu, l0v, 1);
    l0v += __shfl_xor_sync(0xffffffffu, l0v, 2);
    l1v += __shfl_xor_sync(0xffffffffu, l1v, 1);
    l1v += __shfl_xor_sync(0xffffffffu, l1v, 2);
    const float il0 = 1.0f / l0v;
    const float il1 = 1.0f / l1v;

    if ((lane & 3) == 0) {
        invl[(size_t)bh*Sq + r0]     = il0;
        invl[(size_t)bh*Sq + r0 + 8] = il1;
    }

    const int b = bh >> 4, hidx = bh & 15;
#pragma unroll
    for (int j = 0; j < 8; j++) {
        int d = hidx*DKq + 8*j + 2*(lane & 3);
        size_t idx0 = ((size_t)(b*Sq + r0))*Dm + d;
        split2(ctx[j][0]*il0, ctx[j][1]*il0, ctxh + idx0, ctxl + idx0);
        size_t idx1 = idx0 + (size_t)8*Dm;
        split2(ctx[j][2]*il1, ctx[j][3]*il1, ctxh + idx1, ctxl + idx1);
    }
}

// ---------------------------------------------------------------------------
// fixup: attn[row][:] *= invl[row]   (one block per row, float4 RMW)
// ---------------------------------------------------------------------------
__global__ __launch_bounds__(256) void fixup_kernel(
    float* __restrict__ attn, const float* __restrict__ invl)
{
    const size_t row = blockIdx.x;
    const float s = invl[row];
    float4* p = (float4*)(attn + row * Sq);
    const int t = threadIdx.x;
    float4 a = p[t], b = p[t + 256];
    a.x *= s; a.y *= s; a.z *= s; a.w *= s;
    b.x *= s; b.y *= s; b.z *= s; b.w *= s;
    p[t] = a;
    p[t + 256] = b;
}

// ---------------------------------------------------------------------------
extern "C" void kernel_launch(void* const* d_in, const int* in_sizes, int n_in,
                              void* d_out, int out_size)
{
    const float* x  = (const float*)d_in[0];
    const float* Wq = (const float*)d_in[1];
    const float* bq = (const float*)d_in[2];
    const float* Wk = (const float*)d_in[3];
    const float* bk = (const float*)d_in[4];
    const float* Wv = (const float*)d_in[5];
    const float* bv = (const float*)d_in[6];
    const float* Wo = (const float*)d_in[7];
    const float* bo = (const float*)d_in[8];

    float* out  = (float*)d_out;
    float* attn = out + (size_t)NROWS * Dm;

    bf16 *xh, *xl, *wh, *wl, *qh, *ql, *kh, *kl, *vh, *vl, *ch, *cl;
    float* invl;
    cudaGetSymbolAddress((void**)&xh, g_xh); cudaGetSymbolAddress((void**)&xl, g_xl);
    cudaGetSymbolAddress((void**)&wh, g_wh); cudaGetSymbolAddress((void**)&wl, g_wl);
    cudaGetSymbolAddress((void**)&qh, g_qh); cudaGetSymbolAddress((void**)&ql, g_ql);
    cudaGetSymbolAddress((void**)&kh, g_kh); cudaGetSymbolAddress((void**)&kl, g_kl);
    cudaGetSymbolAddress((void**)&vh, g_vh); cudaGetSymbolAddress((void**)&vl, g_vl);
    cudaGetSymbolAddress((void**)&ch, g_ch); cudaGetSymbolAddress((void**)&cl, g_cl);
    cudaGetSymbolAddress((void**)&invl, g_invl);

    const int ntSmem = 2 * NT_STAGE_H * 2;           // 81920 B
    const int faSmem = (2*Q_H + 4*KV_BUF_H) * 2;     // 110592 B
    cudaFuncSetAttribute(gemm_bf16x2_nt, cudaFuncAttributeMaxDynamicSharedMemorySize, ntSmem);
    cudaFuncSetAttribute(attn_fused,     cudaFuncAttributeMaxDynamicSharedMemorySize, faSmem);

    // 1. split inputs into bf16 hi/lo
    split_kernel<<<(NROWS*Dm/4 + 255)/256, 256>>>(x, xh, xl, NROWS*Dm/4);
    const int wq4 = Dm*Dm/4;
    split_kernel<<<(wq4+255)/256, 256>>>(Wq, wh,           wl,           wq4);
    split_kernel<<<(wq4+255)/256, 256>>>(Wk, wh + Dm*Dm,   wl + Dm*Dm,   wq4);
    split_kernel<<<(wq4+255)/256, 256>>>(Wv, wh + 2*Dm*Dm, wl + 2*Dm*Dm, wq4);
    split_kernel<<<(wq4+255)/256, 256>>>(Wo, wh + 3*Dm*Dm, wl + 3*Dm*Dm, wq4);

    // 2. Q/K/V projections. Q pre-scaled by 0.125*log2(e).
    const float QSCALE = 0.18033688011112042f;  // log2(e)/8
    dim3 gProj(Dm/128, NROWS/128);
    gemm_bf16x2_nt<<<gProj, 256, ntSmem>>>(xh, xl, Dm, wh,           wl,           Dm,
                                           bq, nullptr, 0, qh, ql, Dm, QSCALE, 0);
    gemm_bf16x2_nt<<<gProj, 256, ntSmem>>>(xh, xl, Dm, wh + Dm*Dm,   wl + Dm*Dm,   Dm,
                                           bk, nullptr, 0, kh, kl, Dm, 1.f, 0);
    gemm_bf16x2_nt<<<gProj, 256, ntSmem>>>(xh, xl, Dm, wh + 2*Dm*Dm, wl + 2*Dm*Dm, Dm,
                                           bv, nullptr, 0, vh, vl, Dm, 1.f, 0);

    // 3. fused attention (writes unnormalized attn + normalized ctx)
    dim3 gAttn(Sq/128, BH);   // (16, 32)
    attn_fused<<<gAttn, 256, faSmem>>>(qh, ql, kh, kl, vh, vl, attn, invl, ch, cl);

    // 4. normalize attn rows
    fixup_kernel<<<BH*Sq, 256>>>(attn, invl);

    // 5. output projection
    gemm_bf16x2_nt<<<gProj, 256, ntSmem>>>(ch, cl, Dm, wh + 3*Dm*Dm, wl + 3*Dm*Dm, Dm,
                                           bo, out, Dm, nullptr, nullptr, Dm, 1.f, 1);
}

// round 7
// speedup vs baseline: 2.9693x; 1.0548x over previous
#include <cuda_runtime.h>
#include <cuda_bf16.h>

#define Bq 2
#define Sq 2048
#define Dm 1024
#define Hh 16
#define DKq 64
#define NROWS (Bq*Sq)      // 4096
#define BH (Bq*Hh)         // 32

typedef __nv_bfloat16 bf16;

// -------- device scratch (allocation-free rule: __device__ globals) ---------
__device__ bf16 g_xh[NROWS*Dm], g_xl[NROWS*Dm];
__device__ bf16 g_wh[4*Dm*Dm],  g_wl[4*Dm*Dm];
__device__ bf16 g_qh[BH*Sq*DKq], g_ql[BH*Sq*DKq];
__device__ bf16 g_kh[BH*Sq*DKq], g_kl[BH*Sq*DKq];
__device__ bf16 g_vh[BH*Sq*DKq], g_vl[BH*Sq*DKq];
__device__ bf16 g_ch[NROWS*Dm], g_cl[NROWS*Dm];
__device__ float g_invl[BH*Sq];         // per-row 1/sum

// ------------------------------- PTX helpers --------------------------------
#define LDSM4(r0,r1,r2,r3,addr) \
    asm volatile("ldmatrix.sync.aligned.m8n8.x4.shared.b16 {%0,%1,%2,%3},[%4];" \
                 : "=r"(r0),"=r"(r1),"=r"(r2),"=r"(r3) : "r"(addr))
#define LDSM4T(r0,r1,r2,r3,addr) \
    asm volatile("ldmatrix.sync.aligned.m8n8.x4.trans.shared.b16 {%0,%1,%2,%3},[%4];" \
                 : "=r"(r0),"=r"(r1),"=r"(r2),"=r"(r3) : "r"(addr))
#define MMA16816(ac,a,b) \
    asm volatile("mma.sync.aligned.m16n8k16.row.col.f32.bf16.bf16.f32 " \
                 "{%0,%1,%2,%3},{%4,%5,%6,%7},{%8,%9},{%0,%1,%2,%3};" \
                 : "+f"((ac)[0]),"+f"((ac)[1]),"+f"((ac)[2]),"+f"((ac)[3]) \
                 : "r"((a)[0]),"r"((a)[1]),"r"((a)[2]),"r"((a)[3]), \
                   "r"((b)[0]),"r"((b)[1]))
#define CPASYNC16(dst,src) \
    asm volatile("cp.async.cg.shared.global [%0],[%1],16;" \
                 :: "r"(dst), "l"(__cvta_generic_to_global((const void*)(src))))
#define CPCOMMIT asm volatile("cp.async.commit_group;")
#define CPWAIT0  asm volatile("cp.async.wait_group 0;")

__device__ __forceinline__ unsigned smaddr(const void* p) {
    return (unsigned)__cvta_generic_to_shared(p);
}

__device__ __forceinline__ float ex2(float x) {
    float r;
    asm("ex2.approx.f32 %0, %1;" : "=f"(r) : "f"(x));
    return r;
}

__device__ __forceinline__ unsigned pack_bf16x2(float hi, float lo) {
    unsigned r;
    asm("cvt.rn.bf16x2.f32 %0, %1, %2;" : "=r"(r) : "f"(hi), "f"(lo));
    return r;
}

__device__ __forceinline__ void split2(float x, float y, bf16* hp, bf16* lp) {
    unsigned h = pack_bf16x2(y, x);
    float rx = x - __uint_as_float(h << 16);
    float ry = y - __uint_as_float(h & 0xffff0000u);
    unsigned l = pack_bf16x2(ry, rx);
    *(unsigned*)hp = h;
    *(unsigned*)lp = l;
}

// ------------------------------- split kernels ------------------------------
__global__ __launch_bounds__(256) void split_kernel(
    const float* __restrict__ src, bf16* __restrict__ hi, bf16* __restrict__ lo, int n4)
{
    int i = blockIdx.x * blockDim.x + threadIdx.x;
    if (i >= n4) return;
    float4 v = ((const float4*)src)[i];
    split2(v.x, v.y, hi + (size_t)i*4,     lo + (size_t)i*4);
    split2(v.z, v.w, hi + (size_t)i*4 + 2, lo + (size_t)i*4 + 2);
}

// all 4 weight matrices in one launch (z selects the source)
__global__ __launch_bounds__(256) void wsplit_kernel(
    const float* __restrict__ w0, const float* __restrict__ w1,
    const float* __restrict__ w2, const float* __restrict__ w3,
    bf16* __restrict__ hi, bf16* __restrict__ lo)
{
    const int z = blockIdx.z;
    const float* src = (z == 0) ? w0 : (z == 1) ? w1 : (z == 2) ? w2 : w3;
    bf16* h = hi + (size_t)z * Dm * Dm;
    bf16* l = lo + (size_t)z * Dm * Dm;
    int i = blockIdx.x * blockDim.x + threadIdx.x;
    if (i >= Dm*Dm/4) return;
    float4 v = ((const float4*)src)[i];
    split2(v.x, v.y, h + (size_t)i*4,     l + (size_t)i*4);
    split2(v.z, v.w, h + (size_t)i*4 + 2, l + (size_t)i*4 + 2);
}

// ---------------------------------------------------------------------------
// Generic NT GEMM on hi/lo bf16 pairs (projections).
// mode 0: head-split bf16 hi/lo out, value scaled by `scale` after bias.
// mode 1: fp32 rows out.
// ---------------------------------------------------------------------------
#define NT_STAGE_H 20480

__device__ __forceinline__ void nt_load(
    unsigned sb,
    const bf16* __restrict__ Ah, const bf16* __restrict__ Al,
    const bf16* __restrict__ Wh, const bf16* __restrict__ Wl,
    int lda, int ldw, int m0, int n0, int kt, int t)
{
#pragma unroll
    for (int j = 0; j < 2; j++) {
        int idx = t + j*256;
        int row = idx >> 2;
        int q   = (idx & 3) * 8;
        unsigned so = (unsigned)(row*40 + q) * 2;
        CPASYNC16(sb + so,               Ah + (size_t)(m0+row)*lda + kt + q);
        CPASYNC16(sb + 5120*2  + so,     Al + (size_t)(m0+row)*lda + kt + q);
        CPASYNC16(sb + 10240*2 + so,     Wh + (size_t)(n0+row)*ldw + kt + q);
        CPASYNC16(sb + 15360*2 + so,     Wl + (size_t)(n0+row)*ldw + kt + q);
    }
}

__global__ __launch_bounds__(256) void gemm_bf16x2_nt(
    const bf16* __restrict__ Ah, const bf16* __restrict__ Al, int lda,
    const bf16* __restrict__ Wh, const bf16* __restrict__ Wl, int ldw,
    const float* __restrict__ bias,
    float* __restrict__ outF, int ldc,
    bf16* __restrict__ outHi, bf16* __restrict__ outLo,
    int K, float scale, int mode)
{
    extern __shared__ bf16 sm[];
    const int t    = threadIdx.x;
    const int lane = t & 31;
    const int wid  = t >> 5;
    const int warp_m = wid >> 2;
    const int warp_n = wid & 3;
    const int m0 = blockIdx.y * 128;
    const int n0 = blockIdx.x * 128;

    float acc[4][4][4];
#pragma unroll
    for (int i = 0; i < 4; i++)
#pragma unroll
        for (int j = 0; j < 4; j++)
#pragma unroll
            for (int r = 0; r < 4; r++) acc[i][j][r] = 0.f;

    const unsigned s0 = smaddr(sm);
    const int nk = K / 32;

    nt_load(s0, Ah, Al, Wh, Wl, lda, ldw, m0, n0, 0, t);
    CPCOMMIT;

    for (int i = 0; i < nk; i++) {
        CPWAIT0;
        __syncthreads();
        if (i + 1 < nk) {
            nt_load(s0 + ((i+1)&1)*NT_STAGE_H*2, Ah, Al, Wh, Wl, lda, ldw,
                    m0, n0, (i+1)*32, t);
            CPCOMMIT;
        }
        unsigned sb = s0 + (i&1)*NT_STAGE_H*2;

#pragma unroll
        for (int k16 = 0; k16 < 32; k16 += 16) {
            unsigned ah[4][4], al[4][4], bh[4][2], bl[4][2];
            int arow = warp_m*64 + (lane & 15);
            int acol = k16 + ((lane >> 4) << 3);
#pragma unroll
            for (int mt = 0; mt < 4; mt++) {
                unsigned ad = sb + (unsigned)((arow + mt*16)*40 + acol)*2;
                LDSM4(ah[mt][0], ah[mt][1], ah[mt][2], ah[mt][3], ad);
                LDSM4(al[mt][0], al[mt][1], al[mt][2], al[mt][3], ad + 5120*2);
            }
            int brow = warp_n*32 + ((lane >> 4) << 3) + (lane & 7);
            int bcol = k16 + (((lane >> 3) & 1) << 3);
#pragma unroll
            for (int pr = 0; pr < 2; pr++) {
                unsigned bd = sb + 10240*2 + (unsigned)((brow + pr*16)*40 + bcol)*2;
                unsigned r0, r1, r2, r3;
                LDSM4(r0, r1, r2, r3, bd);
                bh[pr*2][0] = r0; bh[pr*2][1] = r1;
                bh[pr*2+1][0] = r2; bh[pr*2+1][1] = r3;
                LDSM4(r0, r1, r2, r3, bd + 5120*2);
                bl[pr*2][0] = r0; bl[pr*2][1] = r1;
                bl[pr*2+1][0] = r2; bl[pr*2+1][1] = r3;
            }
#pragma unroll
            for (int mt = 0; mt < 4; mt++)
#pragma unroll
                for (int nt = 0; nt < 4; nt++) {
                    MMA16816(acc[mt][nt], ah[mt], bh[nt]);
                    MMA16816(acc[mt][nt], ah[mt], bl[nt]);
                    MMA16816(acc[mt][nt], al[mt], bh[nt]);
                }
        }
    }

#pragma unroll
    for (int mt = 0; mt < 4; mt++)
#pragma unroll
        for (int nt = 0; nt < 4; nt++) {
            int r = m0 + warp_m*64 + mt*16 + (lane >> 2);
            int c = n0 + warp_n*32 + nt*8 + ((lane & 3) << 1);
            float v00 = acc[mt][nt][0] + bias[c];
            float v01 = acc[mt][nt][1] + bias[c+1];
            float v10 = acc[mt][nt][2] + bias[c];
            float v11 = acc[mt][nt][3] + bias[c+1];
            if (mode == 1) {
                *(float2*)&outF[(size_t)r*ldc + c]     = make_float2(v00, v01);
                *(float2*)&outF[(size_t)(r+8)*ldc + c] = make_float2(v10, v11);
            } else {
                v00 *= scale; v01 *= scale; v10 *= scale; v11 *= scale;
                int b = r >> 11, s = r & 2047;
                int h = c >> 6,  dk = c & 63;
                size_t base = (((size_t)(b*Hh + h))*Sq + s)*DKq + dk;
                split2(v00, v01, outHi + base, outLo + base);
                split2(v10, v11, outHi + base + 8*DKq, outLo + base + 8*DKq);
            }
        }
}

// ---------------------------------------------------------------------------
// Fused attention (single pass over K/V).
// Q pre-scaled by 0.125*log2(e): p = 2^(q.k) = exp(score).
// Writes UNNORMALIZED p to attn; accumulates l per row and ctx = sum p*V;
// ctx normalized in-register. Fixup kernel normalizes attn afterwards.
// ---------------------------------------------------------------------------
#define KT 64
#define KV_BUF_H 9216
#define Q_H 9216

__device__ __forceinline__ void load_kv_tile(
    unsigned dsth, const bf16* __restrict__ gh, const bf16* __restrict__ gl,
    int row0, int t)
{
#pragma unroll
    for (int j = 0; j < 2; j++) {
        int c = t + j*256;
        int row = c >> 3, q = (c & 7)*8;
        unsigned so = (unsigned)(row*72 + q)*2;
        CPASYNC16(dsth + so,          gh + (size_t)(row0+row)*DKq + q);
        CPASYNC16(dsth + 4608*2 + so, gl + (size_t)(row0+row)*DKq + q);
    }
}

__device__ __forceinline__ void compute_s(
    float s[8][4], const unsigned qfh[4][4], const unsigned qfl[4][4],
    unsigned kbuf, int lane)
{
#pragma unroll
    for (int j = 0; j < 8; j++)
#pragma unroll
        for (int r = 0; r < 4; r++) s[j][r] = 0.f;

    const int rbase = ((lane >> 4) << 3) + (lane & 7);
#pragma unroll
    for (int f = 0; f < 4; f++) {
        const int cbase = f*16 + (((lane >> 3) & 1) << 3);
#pragma unroll
        for (int pr = 0; pr < 4; pr++) {
            unsigned off = (unsigned)((pr*16 + rbase)*72 + cbase)*2;
            unsigned h0,h1,h2,h3, l0,l1,l2,l3;
            LDSM4(h0,h1,h2,h3, kbuf + off);
            LDSM4(l0,l1,l2,l3, kbuf + 4608*2 + off);
            unsigned bh0[2]={h0,h1}, bh1[2]={h2,h3};
            unsigned bl0[2]={l0,l1}, bl1[2]={l2,l3};
            MMA16816(s[2*pr],   qfh[f], bh0);
            MMA16816(s[2*pr],   qfh[f], bl0);
            MMA16816(s[2*pr],   qfl[f], bh0);
            MMA16816(s[2*pr+1], qfh[f], bh1);
            MMA16816(s[2*pr+1], qfh[f], bl1);
            MMA16816(s[2*pr+1], qfl[f], bh1);
        }
    }
}

__global__ __launch_bounds__(256) void attn_fused(
    const bf16* __restrict__ qh_g, const bf16* __restrict__ ql_g,
    const bf16* __restrict__ kh_g, const bf16* __restrict__ kl_g,
    const bf16* __restrict__ vh_g, const bf16* __restrict__ vl_g,
    float* __restrict__ attn, float* __restrict__ invl,
    bf16* __restrict__ ctxh, bf16* __restrict__ ctxl)
{
    extern __shared__ bf16 smb[];
    const int t = threadIdx.x, lane = t & 31, warp = t >> 5;
    const int bh = blockIdx.y, q0 = blockIdx.x * 128;
    const bf16* Qh = qh_g + (size_t)bh*Sq*DKq;
    const bf16* Ql = ql_g + (size_t)bh*Sq*DKq;
    const bf16* Kh = kh_g + (size_t)bh*Sq*DKq;
    const bf16* Kl = kl_g + (size_t)bh*Sq*DKq;
    const bf16* Vh = vh_g + (size_t)bh*Sq*DKq;
    const bf16* Vl = vl_g + (size_t)bh*Sq*DKq;

    const unsigned s0 = smaddr(smb);
    const unsigned qb = s0;
    const unsigned kb = s0 + 2*Q_H*2;
    const unsigned vb = kb + 2*KV_BUF_H*2;

#pragma unroll
    for (int j = 0; j < 4; j++) {
        int c = t + j*256;
        int row = c >> 3, q = (c & 7)*8;
        unsigned so = (unsigned)(row*72 + q)*2;
        CPASYNC16(qb + so,         Qh + (size_t)(q0+row)*DKq + q);
        CPASYNC16(qb + Q_H*2 + so, Ql + (size_t)(q0+row)*DKq + q);
    }
    load_kv_tile(kb, Kh, Kl, 0, t);
    load_kv_tile(vb, Vh, Vl, 0, t);
    CPCOMMIT;
    CPWAIT0;
    __syncthreads();

    unsigned qfh[4][4], qfl[4][4];
    {
        int arow = warp*16 + (lane & 15);
#pragma unroll
        for (int f = 0; f < 4; f++) {
            unsigned ad = qb + (unsigned)(arow*72 + f*16 + ((lane >> 4) << 3))*2;
            LDSM4(qfh[f][0], qfh[f][1], qfh[f][2], qfh[f][3], ad);
            LDSM4(qfl[f][0], qfl[f][1], qfl[f][2], qfl[f][3], ad + Q_H*2);
        }
    }

    const int g = lane >> 2;
    const int r0 = q0 + warp*16 + g;
    float* aptr0 = attn + ((size_t)bh*Sq + r0)*Sq + 2*(lane & 3);
    float* aptr1 = aptr0 + (size_t)8*Sq;

    float ctx[8][4];
#pragma unroll
    for (int j = 0; j < 8; j++)
#pragma unroll
        for (int r = 0; r < 4; r++) ctx[j][r] = 0.f;

    float l0v = 0.f, l1v = 0.f;
    const int nk = Sq / KT;

    for (int i = 0; i < nk; i++) {
        if (i > 0) { CPWAIT0; __syncthreads(); }
        if (i + 1 < nk) {
            load_kv_tile(kb + ((i+1)&1)*KV_BUF_H*2, Kh, Kl, (i+1)*KT, t);
            load_kv_tile(vb + ((i+1)&1)*KV_BUF_H*2, Vh, Vl, (i+1)*KT, t);
            CPCOMMIT;
        }
        float s[8][4];
        compute_s(s, qfh, qfl, kb + (i&1)*KV_BUF_H*2, lane);

        const int k0 = i*KT;
#pragma unroll
        for (int j = 0; j < 8; j++) {
            float p0 = ex2(s[j][0]);
            float p1 = ex2(s[j][1]);
            float p2 = ex2(s[j][2]);
            float p3 = ex2(s[j][3]);
            *(float2*)(aptr0 + k0 + 8*j) = make_float2(p0, p1);
            *(float2*)(aptr1 + k0 + 8*j) = make_float2(p2, p3);
            l0v += p0 + p1;
            l1v += p2 + p3;
            s[j][0] = p0; s[j][1] = p1; s[j][2] = p2; s[j][3] = p3;
        }

        const unsigned vbuf = vb + (i&1)*KV_BUF_H*2;
#pragma unroll
        for (int f = 0; f < 4; f++) {
            unsigned pah[4], pal[4];
#pragma unroll
            for (int u = 0; u < 2; u++) {
                const float* pv = s[2*f + u];
                unsigned h0 = pack_bf16x2(pv[1], pv[0]);
                float e0 = pv[0] - __uint_as_float(h0 << 16);
                float e1 = pv[1] - __uint_as_float(h0 & 0xffff0000u);
                pal[2*u]   = pack_bf16x2(e1, e0);
                pah[2*u]   = h0;
                unsigned h1 = pack_bf16x2(pv[3], pv[2]);
                float e2 = pv[2] - __uint_as_float(h1 << 16);
                float e3 = pv[3] - __uint_as_float(h1 & 0xffff0000u);
                pal[2*u+1] = pack_bf16x2(e3, e2);
                pah[2*u+1] = h1;
            }
            unsigned pahf[4] = {pah[0], pah[1], pah[2], pah[3]};
            unsigned palf[4] = {pal[0], pal[1], pal[2], pal[3]};

#pragma unroll
            for (int pr = 0; pr < 4; pr++) {
                unsigned off = (unsigned)((f*16 + (lane & 15))*72
                               + pr*16 + ((lane >> 4) << 3))*2;
                unsigned h0,h1,h2,h3, l0,l1,l2,l3;
                LDSM4T(h0,h1,h2,h3, vbuf + off);
                LDSM4T(l0,l1,l2,l3, vbuf + 4608*2 + off);
                unsigned bh0[2]={h0,h1}, bh1[2]={h2,h3};
                unsigned bl0[2]={l0,l1}, bl1[2]={l2,l3};
                MMA16816(ctx[2*pr],   pahf, bh0);
                MMA16816(ctx[2*pr],   pahf, bl0);
                MMA16816(ctx[2*pr],   palf, bh0);
                MMA16816(ctx[2*pr+1], pahf, bh1);
                MMA16816(ctx[2*pr+1], pahf, bl1);
                MMA16816(ctx[2*pr+1], palf, bh1);
            }
        }
        __syncthreads();
    }

    l0v += __shfl_xor_sync(0xffffffffu, l0v, 1);
    l0v += __shfl_xor_sync(0xffffffffu, l0v, 2);
    l1v += __shfl_xor_sync(0xffffffffu, l1v, 1);
    l1v += __shfl_xor_sync(0xffffffffu, l1v, 2);
    const float il0 = 1.0f / l0v;
    const float il1 = 1.0f / l1v;

    if ((lane & 3) == 0) {
        invl[(size_t)bh*Sq + r0]     = il0;
        invl[(size_t)bh*Sq + r0 + 8] = il1;
    }

    const int b = bh >> 4, hidx = bh & 15;
#pragma unroll
    for (int j = 0; j < 8; j++) {
        int d = hidx*DKq + 8*j + 2*(lane & 3);
        size_t idx0 = ((size_t)(b*Sq + r0))*Dm + d;
        split2(ctx[j][0]*il0, ctx[j][1]*il0, ctxh + idx0, ctxl + idx0);
        size_t idx1 = idx0 + (size_t)8*Dm;
        split2(ctx[j][2]*il1, ctx[j][3]*il1, ctxh + idx1, ctxl + idx1);
    }
}

// ---------------------------------------------------------------------------
// fixup: attn[row][:] *= invl[row]
// ---------------------------------------------------------------------------
__global__ __launch_bounds__(256) void fixup_kernel(
    float* __restrict__ attn, const float* __restrict__ invl)
{
    const size_t row = blockIdx.x;
    const float s = invl[row];
    float4* p = (float4*)(attn + row * Sq);
    const int t = threadIdx.x;
    float4 a = p[t], b = p[t + 256];
    a.x *= s; a.y *= s; a.z *= s; a.w *= s;
    b.x *= s; b.y *= s; b.z *= s; b.w *= s;
    p[t] = a;
    p[t + 256] = b;
}

// ---------------------------------------------------------------------------
extern "C" void kernel_launch(void* const* d_in, const int* in_sizes, int n_in,
                              void* d_out, int out_size)
{
    const float* x  = (const float*)d_in[0];
    const float* Wq = (const float*)d_in[1];
    const float* bq = (const float*)d_in[2];
    const float* Wk = (const float*)d_in[3];
    const float* bk = (const float*)d_in[4];
    const float* Wv = (const float*)d_in[5];
    const float* bv = (const float*)d_in[6];
    const float* Wo = (const float*)d_in[7];
    const float* bo = (const float*)d_in[8];

    float* out  = (float*)d_out;
    float* attn = out + (size_t)NROWS * Dm;

    bf16 *xh, *xl, *wh, *wl, *qh, *ql, *kh, *kl, *vh, *vl, *ch, *cl;
    float* invl;
    cudaGetSymbolAddress((void**)&xh, g_xh); cudaGetSymbolAddress((void**)&xl, g_xl);
    cudaGetSymbolAddress((void**)&wh, g_wh); cudaGetSymbolAddress((void**)&wl, g_wl);
    cudaGetSymbolAddress((void**)&qh, g_qh); cudaGetSymbolAddress((void**)&ql, g_ql);
    cudaGetSymbolAddress((void**)&kh, g_kh); cudaGetSymbolAddress((void**)&kl, g_kl);
    cudaGetSymbolAddress((void**)&vh, g_vh); cudaGetSymbolAddress((void**)&vl, g_vl);
    cudaGetSymbolAddress((void**)&ch, g_ch); cudaGetSymbolAddress((void**)&cl, g_cl);
    cudaGetSymbolAddress((void**)&invl, g_invl);

    const int ntSmem = 2 * NT_STAGE_H * 2;           // 81920 B
    const int faSmem = (2*Q_H + 4*KV_BUF_H) * 2;     // 110592 B
    cudaFuncSetAttribute(gemm_bf16x2_nt, cudaFuncAttributeMaxDynamicSharedMemorySize, ntSmem);
    cudaFuncSetAttribute(attn_fused,     cudaFuncAttributeMaxDynamicSharedMemorySize, faSmem);

    // side stream + events (created per call; host-side ops, graph-capture safe)
    cudaStream_t s2;
    cudaStreamCreate(&s2);
    cudaEvent_t evF1, evJ1, evF2, evJ2;
    cudaEventCreateWithFlags(&evF1, cudaEventDisableTiming);
    cudaEventCreateWithFlags(&evJ1, cudaEventDisableTiming);
    cudaEventCreateWithFlags(&evF2, cudaEventDisableTiming);
    cudaEventCreateWithFlags(&evJ2, cudaEventDisableTiming);

    // ---- fork 1: W splits (s2) || x split (main) ----
    cudaEventRecord(evF1, 0);
    cudaStreamWaitEvent(s2, evF1, 0);

    const int wq4 = Dm*Dm/4;
    dim3 gW((wq4 + 255)/256, 1, 4);
    wsplit_kernel<<<gW, 256, 0, s2>>>(Wq, Wk, Wv, Wo, wh, wl);
    split_kernel<<<(NROWS*Dm/4 + 255)/256, 256>>>(x, xh, xl, NROWS*Dm/4);

    cudaEventRecord(evJ1, s2);
    cudaStreamWaitEvent(0, evJ1, 0);

    // ---- Q/K/V projections (main). Q pre-scaled by 0.125*log2(e). ----
    const float QSCALE = 0.18033688011112042f;  // log2(e)/8
    dim3 gProj(Dm/128, NROWS/128);
    gemm_bf16x2_nt<<<gProj, 256, ntSmem>>>(xh, xl, Dm, wh,           wl,           Dm,
                                           bq, nullptr, 0, qh, ql, Dm, QSCALE, 0);
    gemm_bf16x2_nt<<<gProj, 256, ntSmem>>>(xh, xl, Dm, wh + Dm*Dm,   wl + Dm*Dm,   Dm,
                                           bk, nullptr, 0, kh, kl, Dm, 1.f, 0);
    gemm_bf16x2_nt<<<gProj, 256, ntSmem>>>(xh, xl, Dm, wh + 2*Dm*Dm, wl + 2*Dm*Dm, Dm,
                                           bv, nullptr, 0, vh, vl, Dm, 1.f, 0);

    // ---- fused attention ----
    dim3 gAttn(Sq/128, BH);   // (16, 32)
    attn_fused<<<gAttn, 256, faSmem>>>(qh, ql, kh, kl, vh, vl, attn, invl, ch, cl);

    // ---- fork 2: fixup (s2, DRAM-bound) || O-projection (main, tensor-bound) ----
    cudaEventRecord(evF2, 0);
    cudaStreamWaitEvent(s2, evF2, 0);

    fixup_kernel<<<BH*Sq, 256, 0, s2>>>(attn, invl);

    gemm_bf16x2_nt<<<gProj, 256, ntSmem>>>(ch, cl, Dm, wh + (size_t)3*Dm*Dm,
                                           wl + (size_t)3*Dm*Dm, Dm,
                                           bo, out, Dm, nullptr, nullptr, Dm, 1.f, 1);

    cudaEventRecord(evJ2, s2);
    cudaStreamWaitEvent(0, evJ2, 0);
}